// round 1
// baseline (speedup 1.0000x reference)
#include <cuda_runtime.h>
#include <math.h>

#define TT 256
#define BB 128
#define HH 512
#define DEMB 256
#define PAD_IDX 29999
#define NCLS 5
#define G4H 2048  // 4*HH

// ------------------------- scratch (static device memory, no allocs) ---------
__device__ float g_x0  [(size_t)TT * BB * DEMB];   // embedded input, row = t*B+b
__device__ float g_xg0f[(size_t)TT * BB * G4H];
__device__ float g_xg0r[(size_t)TT * BB * G4H];
__device__ float g_h0  [(size_t)TT * BB * 2 * HH]; // [row][0:512)=hf, [512:1024)=hr
__device__ float g_xg1f[(size_t)TT * BB * G4H];
__device__ float g_xg1r[(size_t)BB * G4H];         // only t = T-1 slice needed
__device__ float g_h1  [2 * BB * HH];              // ping-pong for layer1 fwd
__device__ float g_hr1 [BB * HH];
__device__ int   g_bar0[TT];
__device__ int   g_bar1[TT];

// ------------------------- reset barriers (per graph replay) -----------------
__global__ void reset_kernel() {
    int i = threadIdx.x;
    if (i < TT) { g_bar0[i] = 0; g_bar1[i] = 0; }
}

// ------------------------- embedding gather ----------------------------------
__global__ void embed_kernel(const int* __restrict__ x,
                             const float* __restrict__ emb,
                             float* __restrict__ out) {
    int gid = blockIdx.x * blockDim.x + threadIdx.x;   // over T*B*64 float4
    if (gid >= TT * BB * (DEMB / 4)) return;
    int i4  = gid & 63;
    int row = gid >> 6;          // row = t*B + b
    int t = row / BB;
    int b = row - t * BB;
    int xi = x[b * TT + t];      // x is [B, T]
    float4 v;
    if (xi == PAD_IDX) { v.x = v.y = v.z = v.w = 0.f; }
    else               { v = ((const float4*)emb)[(size_t)xi * 64 + i4]; }
    ((float4*)out)[gid] = v;
}

// ------------------------- fp32 tiled GEMM: C = A * W^T + bias ---------------
// A:[M,K] row-major, W:[N,K] row-major, C:[M,N]. M%128==0, N%128==0, K%16==0.
__global__ __launch_bounds__(256) void gemm_bias(const float* __restrict__ A,
                                                 const float* __restrict__ W,
                                                 const float* __restrict__ bias,
                                                 float* __restrict__ C,
                                                 int M, int N, int K) {
    __shared__ __align__(16) float As[16][132];
    __shared__ __align__(16) float Ws[16][132];
    const int bm = blockIdx.y * 128;
    const int bn = blockIdx.x * 128;
    const int tid = threadIdx.x;
    const int tm = (tid & 15) * 8;
    const int tn = (tid >> 4) * 8;
    const int ra = tid >> 1;         // 0..127
    const int ka = (tid & 1) * 8;    // 0 or 8

    float acc[8][8];
#pragma unroll
    for (int i = 0; i < 8; i++)
#pragma unroll
        for (int j = 0; j < 8; j++) acc[i][j] = 0.f;

    const float* Ap = A + (size_t)(bm + ra) * K + ka;
    const float* Wp = W + (size_t)(bn + ra) * K + ka;

    for (int kb = 0; kb < K; kb += 16) {
        float4 a0 = *(const float4*)(Ap + kb);
        float4 a1 = *(const float4*)(Ap + kb + 4);
        float4 w0 = *(const float4*)(Wp + kb);
        float4 w1 = *(const float4*)(Wp + kb + 4);
        __syncthreads();
        As[ka + 0][ra] = a0.x; As[ka + 1][ra] = a0.y;
        As[ka + 2][ra] = a0.z; As[ka + 3][ra] = a0.w;
        As[ka + 4][ra] = a1.x; As[ka + 5][ra] = a1.y;
        As[ka + 6][ra] = a1.z; As[ka + 7][ra] = a1.w;
        Ws[ka + 0][ra] = w0.x; Ws[ka + 1][ra] = w0.y;
        Ws[ka + 2][ra] = w0.z; Ws[ka + 3][ra] = w0.w;
        Ws[ka + 4][ra] = w1.x; Ws[ka + 5][ra] = w1.y;
        Ws[ka + 6][ra] = w1.z; Ws[ka + 7][ra] = w1.w;
        __syncthreads();
#pragma unroll
        for (int kk = 0; kk < 16; kk++) {
            float av[8], wv[8];
            *(float4*)&av[0] = *(const float4*)&As[kk][tm];
            *(float4*)&av[4] = *(const float4*)&As[kk][tm + 4];
            *(float4*)&wv[0] = *(const float4*)&Ws[kk][tn];
            *(float4*)&wv[4] = *(const float4*)&Ws[kk][tn + 4];
#pragma unroll
            for (int i = 0; i < 8; i++)
#pragma unroll
                for (int j = 0; j < 8; j++) acc[i][j] += av[i] * wv[j];
        }
    }
#pragma unroll
    for (int i = 0; i < 8; i++) {
        size_t row = (size_t)(bm + tm + i) * N + bn;
#pragma unroll
        for (int j = 0; j < 8; j++)
            C[row + tn + j] = acc[i][j] + bias[bn + tn + j];
    }
}

__device__ __forceinline__ float sigmoidf_(float v) { return 1.f / (1.f + expf(-v)); }

// ------------------------- layer-0 scan (both dirs, persistent) --------------
// grid = 128 CTAs (64 fwd + 64 rev), 256 threads.
// CTA: 16 hidden units x 64 batches. Thread: 1 unit (4 gate rows) x 4 batches.
#define S0_SMEM ((512 * 68 + 32 * 68 + 64) * 4)
__global__ __launch_bounds__(256, 1) void scan0_kernel(
    const float* __restrict__ xgf, const float* __restrict__ xgr,
    const float* __restrict__ whhf, const float* __restrict__ whhr,
    const float* __restrict__ bhhf, const float* __restrict__ bhhr,
    float* __restrict__ h0) {
    extern __shared__ __align__(16) float smem[];
    float* Wsm = smem;                 // [512][68] k-major, col = ulocal*4+gate
    float* Hs  = smem + 512 * 68;      // [32][68]  k-major, col = batch-local
    float* bsm = Hs + 32 * 68;         // [64]

    const int dir   = blockIdx.x >> 6;
    const int sub   = blockIdx.x & 63;
    const int j0    = (sub >> 1) * 16;
    const int bbase = (sub & 1) * 64;
    const float* W  = dir ? whhr : whhf;
    const float* bh = dir ? bhhr : bhhf;
    const float* xg = dir ? xgr : xgf;
    const int tid = threadIdx.x;

    for (int idx = tid; idx < 64 * 512; idx += 256) {
        int ucol = idx >> 9, k = idx & 511;
        int u = ucol >> 2, g = ucol & 3;
        Wsm[k * 68 + ucol] = W[(size_t)(g * 512 + j0 + u) * 512 + k];
    }
    if (tid < 64) {
        int u = tid >> 2, g = tid & 3;
        bsm[tid] = bh[g * 512 + j0 + u];
    }
    __syncthreads();

    const int ulocal = tid & 15;
    const int btile  = tid >> 4;       // 0..15
    const int j = j0 + ulocal;
    const int dcol = dir * 512;
    float c[4] = {0.f, 0.f, 0.f, 0.f};

    for (int step = 0; step < TT; step++) {
        const int t = dir ? (TT - 1 - step) : step;
        float acc[16];
#pragma unroll
        for (int a = 0; a < 16; a++) acc[a] = 0.f;

        if (step > 0) {
            const int tprev = dir ? (t + 1) : (t - 1);
            const float* hsrc = h0 + (size_t)tprev * BB * 1024 + dcol;
            for (int kb = 0; kb < 512; kb += 32) {
                __syncthreads();
#pragma unroll
                for (int i = 0; i < 2; i++) {
                    int e = tid + i * 256;
                    int b = e & 63, kg = e >> 6;   // kg 0..7
                    float4 hv = *(const float4*)(hsrc + (size_t)(bbase + b) * 1024 + kb + kg * 4);
                    float* hp = &Hs[(kg * 4) * 68 + b];
                    hp[0] = hv.x; hp[68] = hv.y; hp[136] = hv.z; hp[204] = hv.w;
                }
                __syncthreads();
#pragma unroll
                for (int kk = 0; kk < 32; kk++) {
                    float4 wv = *(const float4*)&Wsm[(kb + kk) * 68 + ulocal * 4];
                    float4 hv = *(const float4*)&Hs[kk * 68 + btile * 4];
                    acc[0]  += hv.x * wv.x; acc[1]  += hv.x * wv.y;
                    acc[2]  += hv.x * wv.z; acc[3]  += hv.x * wv.w;
                    acc[4]  += hv.y * wv.x; acc[5]  += hv.y * wv.y;
                    acc[6]  += hv.y * wv.z; acc[7]  += hv.y * wv.w;
                    acc[8]  += hv.z * wv.x; acc[9]  += hv.z * wv.y;
                    acc[10] += hv.z * wv.z; acc[11] += hv.z * wv.w;
                    acc[12] += hv.w * wv.x; acc[13] += hv.w * wv.y;
                    acc[14] += hv.w * wv.z; acc[15] += hv.w * wv.w;
                }
            }
        }
#pragma unroll
        for (int bi = 0; bi < 4; bi++) {
            int b = bbase + btile * 4 + bi;
            size_t xrow = ((size_t)t * BB + b) * G4H;
            float gi = acc[bi * 4 + 0] + xg[xrow + 0 * 512 + j] + bsm[ulocal * 4 + 0];
            float gf = acc[bi * 4 + 1] + xg[xrow + 1 * 512 + j] + bsm[ulocal * 4 + 1];
            float gg = acc[bi * 4 + 2] + xg[xrow + 2 * 512 + j] + bsm[ulocal * 4 + 2];
            float go = acc[bi * 4 + 3] + xg[xrow + 3 * 512 + j] + bsm[ulocal * 4 + 3];
            float cv = sigmoidf_(gf) * c[bi] + sigmoidf_(gi) * tanhf(gg);
            c[bi] = cv;
            h0[((size_t)t * BB + b) * 1024 + dcol + j] = sigmoidf_(go) * tanhf(cv);
        }
        // global step barrier
        __threadfence();
        __syncthreads();
        if (tid == 0) {
            atomicAdd(&g_bar0[step], 1);
            while (((volatile int*)g_bar0)[step] < 128) {}
        }
        __syncthreads();
    }
}

// ------------------------- layer-1 forward scan (persistent) -----------------
// grid = 128 CTAs, 128 threads. CTA: 16 units x 32 batches.
#define S1_SMEM ((512 * 68 + 32 * 36 + 64) * 4)
__global__ __launch_bounds__(128, 1) void scan1_kernel(
    const float* __restrict__ xg, const float* __restrict__ whh,
    const float* __restrict__ bhh, float* __restrict__ h1) {
    extern __shared__ __align__(16) float smem[];
    float* Wsm = smem;             // [512][68]
    float* Hs  = smem + 512 * 68;  // [32][36]
    float* bsm = Hs + 32 * 36;

    const int j0    = (blockIdx.x >> 2) * 16;
    const int bbase = (blockIdx.x & 3) * 32;
    const int tid = threadIdx.x;

    for (int idx = tid; idx < 64 * 512; idx += 128) {
        int ucol = idx >> 9, k = idx & 511;
        int u = ucol >> 2, g = ucol & 3;
        Wsm[k * 68 + ucol] = whh[(size_t)(g * 512 + j0 + u) * 512 + k];
    }
    if (tid < 64) {
        int u = tid >> 2, g = tid & 3;
        bsm[tid] = bhh[g * 512 + j0 + u];
    }
    __syncthreads();

    const int ulocal = tid & 15;
    const int btile  = tid >> 4;   // 0..7
    const int j = j0 + ulocal;
    float c[4] = {0.f, 0.f, 0.f, 0.f};

    for (int t = 0; t < TT; t++) {
        float acc[16];
#pragma unroll
        for (int a = 0; a < 16; a++) acc[a] = 0.f;

        if (t > 0) {
            const float* hsrc = h1 + (size_t)((t - 1) & 1) * BB * HH;
            for (int kb = 0; kb < 512; kb += 32) {
                __syncthreads();
#pragma unroll
                for (int i = 0; i < 2; i++) {
                    int e = tid + i * 128;
                    int b = e & 31, kg = e >> 5;  // kg 0..7
                    float4 hv = *(const float4*)(hsrc + (size_t)(bbase + b) * HH + kb + kg * 4);
                    float* hp = &Hs[(kg * 4) * 36 + b];
                    hp[0] = hv.x; hp[36] = hv.y; hp[72] = hv.z; hp[108] = hv.w;
                }
                __syncthreads();
#pragma unroll
                for (int kk = 0; kk < 32; kk++) {
                    float4 wv = *(const float4*)&Wsm[(kb + kk) * 68 + ulocal * 4];
                    float4 hv = *(const float4*)&Hs[kk * 36 + btile * 4];
                    acc[0]  += hv.x * wv.x; acc[1]  += hv.x * wv.y;
                    acc[2]  += hv.x * wv.z; acc[3]  += hv.x * wv.w;
                    acc[4]  += hv.y * wv.x; acc[5]  += hv.y * wv.y;
                    acc[6]  += hv.y * wv.z; acc[7]  += hv.y * wv.w;
                    acc[8]  += hv.z * wv.x; acc[9]  += hv.z * wv.y;
                    acc[10] += hv.z * wv.z; acc[11] += hv.z * wv.w;
                    acc[12] += hv.w * wv.x; acc[13] += hv.w * wv.y;
                    acc[14] += hv.w * wv.z; acc[15] += hv.w * wv.w;
                }
            }
        }
#pragma unroll
        for (int bi = 0; bi < 4; bi++) {
            int b = bbase + btile * 4 + bi;
            size_t xrow = ((size_t)t * BB + b) * G4H;
            float gi = acc[bi * 4 + 0] + xg[xrow + 0 * 512 + j] + bsm[ulocal * 4 + 0];
            float gf = acc[bi * 4 + 1] + xg[xrow + 1 * 512 + j] + bsm[ulocal * 4 + 1];
            float gg = acc[bi * 4 + 2] + xg[xrow + 2 * 512 + j] + bsm[ulocal * 4 + 2];
            float go = acc[bi * 4 + 3] + xg[xrow + 3 * 512 + j] + bsm[ulocal * 4 + 3];
            float cv = sigmoidf_(gf) * c[bi] + sigmoidf_(gi) * tanhf(gg);
            c[bi] = cv;
            h1[(size_t)(t & 1) * BB * HH + (size_t)b * HH + j] = sigmoidf_(go) * tanhf(cv);
        }
        __threadfence();
        __syncthreads();
        if (tid == 0) {
            atomicAdd(&g_bar1[t], 1);
            while (((volatile int*)g_bar1)[t] < 128) {}
        }
        __syncthreads();
    }
}

// ------------------------- layer-1 reverse at t = T-1 (one step, zero state) -
__global__ void hr_last_kernel(const float* __restrict__ xg,
                               const float* __restrict__ bhh,
                               float* __restrict__ hr) {
    int idx = blockIdx.x * blockDim.x + threadIdx.x;  // 128*512
    if (idx >= BB * HH) return;
    int b = idx >> 9, j = idx & 511;
    float gi = xg[(size_t)b * G4H + j]        + bhh[j];
    float gg = xg[(size_t)b * G4H + 1024 + j] + bhh[1024 + j];
    float go = xg[(size_t)b * G4H + 1536 + j] + bhh[1536 + j];
    float cv = sigmoidf_(gi) * tanhf(gg);
    hr[idx] = sigmoidf_(go) * tanhf(cv);
}

// ------------------------- final projection [128,5] --------------------------
__global__ void out_kernel(const float* __restrict__ hf, const float* __restrict__ hr,
                           const float* __restrict__ wout, const float* __restrict__ bout,
                           float* __restrict__ out) {
    int b = blockIdx.x;
    int warp = threadIdx.x >> 5;   // 0..4 = class
    int lane = threadIdx.x & 31;
    float s = 0.f;
    for (int k = lane; k < 512; k += 32) s += hf[(size_t)b * HH + k] * wout[warp * 1024 + k];
    for (int k = lane; k < 512; k += 32) s += hr[(size_t)b * HH + k] * wout[warp * 1024 + 512 + k];
#pragma unroll
    for (int off = 16; off; off >>= 1) s += __shfl_xor_sync(0xffffffffu, s, off);
    if (lane == 0) out[b * NCLS + warp] = s + bout[warp];
}

// ------------------------- host launch ---------------------------------------
extern "C" void kernel_launch(void* const* d_in, const int* in_sizes, int n_in,
                              void* d_out, int out_size) {
    const int*   x     = (const int*)  d_in[0];
    const float* emb   = (const float*)d_in[1];
    const float* wih0f = (const float*)d_in[2];
    const float* whh0f = (const float*)d_in[3];
    const float* bih0f = (const float*)d_in[4];
    const float* bhh0f = (const float*)d_in[5];
    const float* wih0r = (const float*)d_in[6];
    const float* whh0r = (const float*)d_in[7];
    const float* bih0r = (const float*)d_in[8];
    const float* bhh0r = (const float*)d_in[9];
    const float* wih1f = (const float*)d_in[10];
    const float* whh1f = (const float*)d_in[11];
    const float* bih1f = (const float*)d_in[12];
    const float* bhh1f = (const float*)d_in[13];
    const float* wih1r = (const float*)d_in[14];
    const float* whh1r = (const float*)d_in[15];  (void)whh1r; // layer1-rev needs only step 0
    const float* bih1r = (const float*)d_in[16];
    const float* bhh1r = (const float*)d_in[17];
    const float* wout  = (const float*)d_in[18];
    const float* bout  = (const float*)d_in[19];
    float* out = (float*)d_out;

    float *p_x0, *p_xg0f, *p_xg0r, *p_h0, *p_xg1f, *p_xg1r, *p_h1, *p_hr1;
    cudaGetSymbolAddress((void**)&p_x0,   g_x0);
    cudaGetSymbolAddress((void**)&p_xg0f, g_xg0f);
    cudaGetSymbolAddress((void**)&p_xg0r, g_xg0r);
    cudaGetSymbolAddress((void**)&p_h0,   g_h0);
    cudaGetSymbolAddress((void**)&p_xg1f, g_xg1f);
    cudaGetSymbolAddress((void**)&p_xg1r, g_xg1r);
    cudaGetSymbolAddress((void**)&p_h1,   g_h1);
    cudaGetSymbolAddress((void**)&p_hr1,  g_hr1);

    cudaFuncSetAttribute(scan0_kernel, cudaFuncAttributeMaxDynamicSharedMemorySize, S0_SMEM);
    cudaFuncSetAttribute(scan1_kernel, cudaFuncAttributeMaxDynamicSharedMemorySize, S1_SMEM);

    reset_kernel<<<1, 256>>>();
    embed_kernel<<<(TT * BB * (DEMB / 4) + 255) / 256, 256>>>(x, emb, p_x0);

    dim3 gBig(G4H / 128, (TT * BB) / 128);   // (16, 256)
    gemm_bias<<<gBig, 256>>>(p_x0, wih0f, bih0f, p_xg0f, TT * BB, G4H, DEMB);
    gemm_bias<<<gBig, 256>>>(p_x0, wih0r, bih0r, p_xg0r, TT * BB, G4H, DEMB);

    scan0_kernel<<<128, 256, S0_SMEM>>>(p_xg0f, p_xg0r, whh0f, whh0r, bhh0f, bhh0r, p_h0);

    gemm_bias<<<gBig, 256>>>(p_h0, wih1f, bih1f, p_xg1f, TT * BB, G4H, 2 * HH);
    dim3 gLast(G4H / 128, 1);
    gemm_bias<<<gLast, 256>>>(p_h0 + (size_t)(TT - 1) * BB * 1024, wih1r, bih1r,
                              p_xg1r, BB, G4H, 2 * HH);

    scan1_kernel<<<128, 128, S1_SMEM>>>(p_xg1f, whh1f, bhh1f, p_h1);

    hr_last_kernel<<<(BB * HH) / 256, 256>>>(p_xg1r, bhh1r, p_hr1);

    // (T-1) is odd -> final forward state lives in ping-pong buffer 1
    out_kernel<<<BB, 160>>>(p_h1 + BB * HH, p_hr1, wout, bout, out);
}

// round 3
// speedup vs baseline: 1.2371x; 1.2371x over previous
#include <cuda_runtime.h>
#include <cuda_bf16.h>
#include <math.h>
#include <cstdint>

#define TT 256
#define BB 128
#define HH 512
#define DEMB 256
#define PAD_IDX 29999
#define NCLS 5
#define G4H 2048  // 4*HH

__device__ __forceinline__ uint32_t smem_to_u32(const void* p) {
    uint32_t a;
    asm("{ .reg .u64 t; cvta.to.shared.u64 t, %1; cvt.u32.u64 %0, t; }" : "=r"(a) : "l"(p));
    return a;
}

// ========================= scratch (static, no allocs) =======================
__device__ float g_x0  [(size_t)TT * BB * DEMB];
__device__ float g_xg0f[(size_t)TT * BB * G4H];
__device__ float g_xg0r[(size_t)TT * BB * G4H];
__device__ float g_h0  [(size_t)TT * BB * 2 * HH];
__device__ float g_xg1f[(size_t)TT * BB * G4H];
__device__ float g_xg1r[(size_t)BB * G4H];
__device__ float g_h1  [2 * BB * HH];
__device__ float g_hr1 [BB * HH];
__device__ int   g_bar0[TT];
__device__ int   g_bar1[TT];

__global__ void reset_kernel() {
    int i = threadIdx.x;
    if (i < TT) { g_bar0[i] = 0; g_bar1[i] = 0; }
}

// ========================= embedding gather ==================================
__global__ void embed_kernel(const int* __restrict__ x,
                             const float* __restrict__ emb,
                             float* __restrict__ out) {
    int gid = blockIdx.x * blockDim.x + threadIdx.x;
    if (gid >= TT * BB * (DEMB / 4)) return;
    int i4  = gid & 63;
    int row = gid >> 6;
    int t = row / BB;
    int b = row - t * BB;
    int xi = x[b * TT + t];
    float4 v;
    if (xi == PAD_IDX) { v.x = v.y = v.z = v.w = 0.f; }
    else               { v = ((const float4*)emb)[(size_t)xi * 64 + i4]; }
    ((float4*)out)[gid] = v;
}

// ========================= mma.sync bf16 split-3 GEMM ========================
// C[M,N] = A[M,K] * W[N,K]^T + bias.  fp32 in/out, bf16 hi/lo split, fp32 accum.
// Tile: 128x128 per CTA, 8 warps (4 M x 2 N), warp tile 32x64.
#define KC  32
#define LDH 40   // halfword row stride in smem (80 B) -> conflict-free ldmatrix

__device__ __forceinline__ void ldsm4(uint32_t* r, uint32_t addr) {
    asm volatile("ldmatrix.sync.aligned.m8n8.x4.shared.b16 {%0,%1,%2,%3}, [%4];"
        : "=r"(r[0]), "=r"(r[1]), "=r"(r[2]), "=r"(r[3]) : "r"(addr));
}
__device__ __forceinline__ void mma_bf16(float* d, const uint32_t* a,
                                         uint32_t b0, uint32_t b1) {
    asm volatile("mma.sync.aligned.m16n8k16.row.col.f32.bf16.bf16.f32 "
        "{%0,%1,%2,%3}, {%4,%5,%6,%7}, {%8,%9}, {%0,%1,%2,%3};"
        : "+f"(d[0]), "+f"(d[1]), "+f"(d[2]), "+f"(d[3])
        : "r"(a[0]), "r"(a[1]), "r"(a[2]), "r"(a[3]), "r"(b0), "r"(b1));
}
// split one float4 into hi/lo bf16x2 pairs and store 8B to each buffer
__device__ __forceinline__ void split_store(uint32_t hi_addr, uint32_t lo_addr,
                                            float4 v) {
    uint32_t h01, h23;
    asm("cvt.rn.bf16x2.f32 %0, %1, %2;" : "=r"(h01) : "f"(v.y), "f"(v.x));
    asm("cvt.rn.bf16x2.f32 %0, %1, %2;" : "=r"(h23) : "f"(v.w), "f"(v.z));
    float f0 = __uint_as_float(h01 << 16);
    float f1 = __uint_as_float(h01 & 0xffff0000u);
    float f2 = __uint_as_float(h23 << 16);
    float f3 = __uint_as_float(h23 & 0xffff0000u);
    float r0 = v.x - f0, r1 = v.y - f1, r2 = v.z - f2, r3 = v.w - f3;
    uint32_t l01, l23;
    asm("cvt.rn.bf16x2.f32 %0, %1, %2;" : "=r"(l01) : "f"(r1), "f"(r0));
    asm("cvt.rn.bf16x2.f32 %0, %1, %2;" : "=r"(l23) : "f"(r3), "f"(r2));
    asm volatile("st.shared.v2.b32 [%0], {%1, %2};" :: "r"(hi_addr), "r"(h01), "r"(h23) : "memory");
    asm volatile("st.shared.v2.b32 [%0], {%1, %2};" :: "r"(lo_addr), "r"(l01), "r"(l23) : "memory");
}

__global__ __launch_bounds__(256) void gemm_mma(const float* __restrict__ A,
                                                const float* __restrict__ W,
                                                const float* __restrict__ bias,
                                                float* __restrict__ C,
                                                int M, int N, int K) {
    __shared__ __align__(16) __nv_bfloat16 smem[4 * 128 * LDH];
    const uint32_t sb = smem_to_u32(smem);
    const uint32_t AH = sb;
    const uint32_t AL = sb + 128 * LDH * 2;
    const uint32_t BH = sb + 2 * 128 * LDH * 2;
    const uint32_t BL = sb + 3 * 128 * LDH * 2;

    const int tid  = threadIdx.x;
    const int lane = tid & 31;
    const int wid  = tid >> 5;
    const int wm   = wid & 3;   // warp row (4)
    const int wn   = wid >> 2;  // warp col (2)
    const int bm   = blockIdx.y * 128;
    const int bn   = blockIdx.x * 128;

    float acc[2][8][4];
#pragma unroll
    for (int i = 0; i < 2; i++)
#pragma unroll
        for (int j = 0; j < 8; j++)
#pragma unroll
            for (int k = 0; k < 4; k++) acc[i][j][k] = 0.f;

    // per-lane ldmatrix smem offsets (halfword units before *2)
    const uint32_t a_row = lane & 15;             // row within 16
    const uint32_t a_col = (lane >> 4) << 3;      // 0 or 8
    const uint32_t b_n   = (lane & 7) + ((lane >> 4) << 3);
    const uint32_t b_k   = ((lane >> 3) & 1) << 3;

    for (int kb = 0; kb < K; kb += KC) {
        __syncthreads();
        // stage A: 128 rows x 32 cols fp32 -> hi/lo bf16
#pragma unroll
        for (int i = 0; i < 4; i++) {
            int idx = tid + i * 256;            // 0..1023 float4
            int row = idx >> 3, c4 = idx & 7;
            float4 v = *(const float4*)(A + (size_t)(bm + row) * K + kb + c4 * 4);
            uint32_t off = (row * LDH + c4 * 4) * 2;
            split_store(AH + off, AL + off, v);
        }
        // stage B (W): 128 rows x 32 cols
#pragma unroll
        for (int i = 0; i < 4; i++) {
            int idx = tid + i * 256;
            int row = idx >> 3, c4 = idx & 7;
            float4 v = *(const float4*)(W + (size_t)(bn + row) * K + kb + c4 * 4);
            uint32_t off = (row * LDH + c4 * 4) * 2;
            split_store(BH + off, BL + off, v);
        }
        __syncthreads();

#pragma unroll
        for (int ks = 0; ks < KC; ks += 16) {
            uint32_t ah[2][4], al[2][4];
#pragma unroll
            for (int ma = 0; ma < 2; ma++) {
                uint32_t off = ((wm * 32 + ma * 16 + a_row) * LDH + ks + a_col) * 2;
                ldsm4(ah[ma], AH + off);
                ldsm4(al[ma], AL + off);
            }
#pragma unroll
            for (int bg = 0; bg < 4; bg++) {   // 16 n-cols per group
                uint32_t boff = ((wn * 64 + bg * 16 + b_n) * LDH + ks + b_k) * 2;
                uint32_t bh[4], bl[4];
                ldsm4(bh, BH + boff);
                ldsm4(bl, BL + boff);
#pragma unroll
                for (int ma = 0; ma < 2; ma++) {
#pragma unroll
                    for (int na = 0; na < 2; na++) {
                        float* d = acc[ma][bg * 2 + na];
                        mma_bf16(d, ah[ma], bh[na * 2], bh[na * 2 + 1]);
                        mma_bf16(d, ah[ma], bl[na * 2], bl[na * 2 + 1]);
                        mma_bf16(d, al[ma], bh[na * 2], bh[na * 2 + 1]);
                    }
                }
            }
        }
    }

    // epilogue: direct global stores + bias
#pragma unroll
    for (int ma = 0; ma < 2; ma++) {
        int row0 = bm + wm * 32 + ma * 16 + (lane >> 2);
#pragma unroll
        for (int na = 0; na < 8; na++) {
            int col = bn + wn * 64 + na * 8 + (lane & 3) * 2;
            float b0 = bias[col], b1 = bias[col + 1];
            float2 v0 = make_float2(acc[ma][na][0] + b0, acc[ma][na][1] + b1);
            float2 v1 = make_float2(acc[ma][na][2] + b0, acc[ma][na][3] + b1);
            *(float2*)(C + (size_t)row0 * N + col) = v0;
            *(float2*)(C + (size_t)(row0 + 8) * N + col) = v1;
        }
    }
}

__device__ __forceinline__ float sigmoidf_(float v) { return 1.f / (1.f + expf(-v)); }

// ========================= layer-0 scan (fp32, persistent) ===================
#define S0_SMEM ((512 * 68 + 32 * 68 + 64) * 4)
__global__ __launch_bounds__(256, 1) void scan0_kernel(
    const float* __restrict__ xgf, const float* __restrict__ xgr,
    const float* __restrict__ whhf, const float* __restrict__ whhr,
    const float* __restrict__ bhhf, const float* __restrict__ bhhr,
    float* __restrict__ h0) {
    extern __shared__ __align__(16) float smemf[];
    float* Wsm = smemf;
    float* Hs  = smemf + 512 * 68;
    float* bsm = Hs + 32 * 68;

    const int dir   = blockIdx.x >> 6;
    const int sub   = blockIdx.x & 63;
    const int j0    = (sub >> 1) * 16;
    const int bbase = (sub & 1) * 64;
    const float* W  = dir ? whhr : whhf;
    const float* bh = dir ? bhhr : bhhf;
    const float* xg = dir ? xgr : xgf;
    const int tid = threadIdx.x;

    for (int idx = tid; idx < 64 * 512; idx += 256) {
        int ucol = idx >> 9, k = idx & 511;
        int u = ucol >> 2, g = ucol & 3;
        Wsm[k * 68 + ucol] = W[(size_t)(g * 512 + j0 + u) * 512 + k];
    }
    if (tid < 64) {
        int u = tid >> 2, g = tid & 3;
        bsm[tid] = bh[g * 512 + j0 + u];
    }
    __syncthreads();

    const int ulocal = tid & 15;
    const int btile  = tid >> 4;
    const int j = j0 + ulocal;
    const int dcol = dir * 512;
    float c[4] = {0.f, 0.f, 0.f, 0.f};

    for (int step = 0; step < TT; step++) {
        const int t = dir ? (TT - 1 - step) : step;
        float acc[16];
#pragma unroll
        for (int a = 0; a < 16; a++) acc[a] = 0.f;

        if (step > 0) {
            const int tprev = dir ? (t + 1) : (t - 1);
            const float* hsrc = h0 + (size_t)tprev * BB * 1024 + dcol;
            for (int kb = 0; kb < 512; kb += 32) {
                __syncthreads();
#pragma unroll
                for (int i = 0; i < 2; i++) {
                    int e = tid + i * 256;
                    int b = e & 63, kg = e >> 6;
                    float4 hv = *(const float4*)(hsrc + (size_t)(bbase + b) * 1024 + kb + kg * 4);
                    float* hp = &Hs[(kg * 4) * 68 + b];
                    hp[0] = hv.x; hp[68] = hv.y; hp[136] = hv.z; hp[204] = hv.w;
                }
                __syncthreads();
#pragma unroll
                for (int kk = 0; kk < 32; kk++) {
                    float4 wv = *(const float4*)&Wsm[(kb + kk) * 68 + ulocal * 4];
                    float4 hv = *(const float4*)&Hs[kk * 68 + btile * 4];
                    acc[0]  += hv.x * wv.x; acc[1]  += hv.x * wv.y;
                    acc[2]  += hv.x * wv.z; acc[3]  += hv.x * wv.w;
                    acc[4]  += hv.y * wv.x; acc[5]  += hv.y * wv.y;
                    acc[6]  += hv.y * wv.z; acc[7]  += hv.y * wv.w;
                    acc[8]  += hv.z * wv.x; acc[9]  += hv.z * wv.y;
                    acc[10] += hv.z * wv.z; acc[11] += hv.z * wv.w;
                    acc[12] += hv.w * wv.x; acc[13] += hv.w * wv.y;
                    acc[14] += hv.w * wv.z; acc[15] += hv.w * wv.w;
                }
            }
        }
#pragma unroll
        for (int bi = 0; bi < 4; bi++) {
            int b = bbase + btile * 4 + bi;
            size_t xrow = ((size_t)t * BB + b) * G4H;
            float gi = acc[bi * 4 + 0] + xg[xrow + 0 * 512 + j] + bsm[ulocal * 4 + 0];
            float gf = acc[bi * 4 + 1] + xg[xrow + 1 * 512 + j] + bsm[ulocal * 4 + 1];
            float gg = acc[bi * 4 + 2] + xg[xrow + 2 * 512 + j] + bsm[ulocal * 4 + 2];
            float go = acc[bi * 4 + 3] + xg[xrow + 3 * 512 + j] + bsm[ulocal * 4 + 3];
            float cv = sigmoidf_(gf) * c[bi] + sigmoidf_(gi) * tanhf(gg);
            c[bi] = cv;
            h0[((size_t)t * BB + b) * 1024 + dcol + j] = sigmoidf_(go) * tanhf(cv);
        }
        __threadfence();
        __syncthreads();
        if (tid == 0) {
            atomicAdd(&g_bar0[step], 1);
            while (((volatile int*)g_bar0)[step] < 128) {}
        }
        __syncthreads();
    }
}

// ========================= layer-1 forward scan ==============================
#define S1_SMEM ((512 * 68 + 32 * 36 + 64) * 4)
__global__ __launch_bounds__(128, 1) void scan1_kernel(
    const float* __restrict__ xg, const float* __restrict__ whh,
    const float* __restrict__ bhh, float* __restrict__ h1) {
    extern __shared__ __align__(16) float smemf[];
    float* Wsm = smemf;
    float* Hs  = smemf + 512 * 68;
    float* bsm = Hs + 32 * 36;

    const int j0    = (blockIdx.x >> 2) * 16;
    const int bbase = (blockIdx.x & 3) * 32;
    const int tid = threadIdx.x;

    for (int idx = tid; idx < 64 * 512; idx += 128) {
        int ucol = idx >> 9, k = idx & 511;
        int u = ucol >> 2, g = ucol & 3;
        Wsm[k * 68 + ucol] = whh[(size_t)(g * 512 + j0 + u) * 512 + k];
    }
    if (tid < 64) {
        int u = tid >> 2, g = tid & 3;
        bsm[tid] = bhh[g * 512 + j0 + u];
    }
    __syncthreads();

    const int ulocal = tid & 15;
    const int btile  = tid >> 4;
    const int j = j0 + ulocal;
    float c[4] = {0.f, 0.f, 0.f, 0.f};

    for (int t = 0; t < TT; t++) {
        float acc[16];
#pragma unroll
        for (int a = 0; a < 16; a++) acc[a] = 0.f;

        if (t > 0) {
            const float* hsrc = h1 + (size_t)((t - 1) & 1) * BB * HH;
            for (int kb = 0; kb < 512; kb += 32) {
                __syncthreads();
#pragma unroll
                for (int i = 0; i < 2; i++) {
                    int e = tid + i * 128;
                    int b = e & 31, kg = e >> 5;
                    float4 hv = *(const float4*)(hsrc + (size_t)(bbase + b) * HH + kb + kg * 4);
                    float* hp = &Hs[(kg * 4) * 36 + b];
                    hp[0] = hv.x; hp[36] = hv.y; hp[72] = hv.z; hp[108] = hv.w;
                }
                __syncthreads();
#pragma unroll
                for (int kk = 0; kk < 32; kk++) {
                    float4 wv = *(const float4*)&Wsm[(kb + kk) * 68 + ulocal * 4];
                    float4 hv = *(const float4*)&Hs[kk * 36 + btile * 4];
                    acc[0]  += hv.x * wv.x; acc[1]  += hv.x * wv.y;
                    acc[2]  += hv.x * wv.z; acc[3]  += hv.x * wv.w;
                    acc[4]  += hv.y * wv.x; acc[5]  += hv.y * wv.y;
                    acc[6]  += hv.y * wv.z; acc[7]  += hv.y * wv.w;
                    acc[8]  += hv.z * wv.x; acc[9]  += hv.z * wv.y;
                    acc[10] += hv.z * wv.z; acc[11] += hv.z * wv.w;
                    acc[12] += hv.w * wv.x; acc[13] += hv.w * wv.y;
                    acc[14] += hv.w * wv.z; acc[15] += hv.w * wv.w;
                }
            }
        }
#pragma unroll
        for (int bi = 0; bi < 4; bi++) {
            int b = bbase + btile * 4 + bi;
            size_t xrow = ((size_t)t * BB + b) * G4H;
            float gi = acc[bi * 4 + 0] + xg[xrow + 0 * 512 + j] + bsm[ulocal * 4 + 0];
            float gf = acc[bi * 4 + 1] + xg[xrow + 1 * 512 + j] + bsm[ulocal * 4 + 1];
            float gg = acc[bi * 4 + 2] + xg[xrow + 2 * 512 + j] + bsm[ulocal * 4 + 2];
            float go = acc[bi * 4 + 3] + xg[xrow + 3 * 512 + j] + bsm[ulocal * 4 + 3];
            float cv = sigmoidf_(gf) * c[bi] + sigmoidf_(gi) * tanhf(gg);
            c[bi] = cv;
            h1[(size_t)(t & 1) * BB * HH + (size_t)b * HH + j] = sigmoidf_(go) * tanhf(cv);
        }
        __threadfence();
        __syncthreads();
        if (tid == 0) {
            atomicAdd(&g_bar1[t], 1);
            while (((volatile int*)g_bar1)[t] < 128) {}
        }
        __syncthreads();
    }
}

// ========================= layer-1 reverse at t = T-1 ========================
__global__ void hr_last_kernel(const float* __restrict__ xg,
                               const float* __restrict__ bhh,
                               float* __restrict__ hr) {
    int idx = blockIdx.x * blockDim.x + threadIdx.x;
    if (idx >= BB * HH) return;
    int b = idx >> 9, j = idx & 511;
    float gi = xg[(size_t)b * G4H + j]        + bhh[j];
    float gg = xg[(size_t)b * G4H + 1024 + j] + bhh[1024 + j];
    float go = xg[(size_t)b * G4H + 1536 + j] + bhh[1536 + j];
    float cv = sigmoidf_(gi) * tanhf(gg);
    hr[idx] = sigmoidf_(go) * tanhf(cv);
}

// ========================= final projection ==================================
__global__ void out_kernel(const float* __restrict__ hf, const float* __restrict__ hr,
                           const float* __restrict__ wout, const float* __restrict__ bout,
                           float* __restrict__ out) {
    int b = blockIdx.x;
    int warp = threadIdx.x >> 5;
    int lane = threadIdx.x & 31;
    float s = 0.f;
    for (int k = lane; k < 512; k += 32) s += hf[(size_t)b * HH + k] * wout[warp * 1024 + k];
    for (int k = lane; k < 512; k += 32) s += hr[(size_t)b * HH + k] * wout[warp * 1024 + 512 + k];
#pragma unroll
    for (int off = 16; off; off >>= 1) s += __shfl_xor_sync(0xffffffffu, s, off);
    if (lane == 0) out[b * NCLS + warp] = s + bout[warp];
}

// ========================= host launch =======================================
extern "C" void kernel_launch(void* const* d_in, const int* in_sizes, int n_in,
                              void* d_out, int out_size) {
    const int*   x     = (const int*)  d_in[0];
    const float* emb   = (const float*)d_in[1];
    const float* wih0f = (const float*)d_in[2];
    const float* whh0f = (const float*)d_in[3];
    const float* bih0f = (const float*)d_in[4];
    const float* bhh0f = (const float*)d_in[5];
    const float* wih0r = (const float*)d_in[6];
    const float* whh0r = (const float*)d_in[7];
    const float* bih0r = (const float*)d_in[8];
    const float* bhh0r = (const float*)d_in[9];
    const float* wih1f = (const float*)d_in[10];
    const float* whh1f = (const float*)d_in[11];
    const float* bih1f = (const float*)d_in[12];
    const float* bhh1f = (const float*)d_in[13];
    const float* wih1r = (const float*)d_in[14];
    const float* whh1r = (const float*)d_in[15]; (void)whh1r;
    const float* bih1r = (const float*)d_in[16];
    const float* bhh1r = (const float*)d_in[17];
    const float* wout  = (const float*)d_in[18];
    const float* bout  = (const float*)d_in[19];
    float* out = (float*)d_out;

    float *p_x0, *p_xg0f, *p_xg0r, *p_h0, *p_xg1f, *p_xg1r, *p_h1, *p_hr1;
    cudaGetSymbolAddress((void**)&p_x0,   g_x0);
    cudaGetSymbolAddress((void**)&p_xg0f, g_xg0f);
    cudaGetSymbolAddress((void**)&p_xg0r, g_xg0r);
    cudaGetSymbolAddress((void**)&p_h0,   g_h0);
    cudaGetSymbolAddress((void**)&p_xg1f, g_xg1f);
    cudaGetSymbolAddress((void**)&p_xg1r, g_xg1r);
    cudaGetSymbolAddress((void**)&p_h1,   g_h1);
    cudaGetSymbolAddress((void**)&p_hr1,  g_hr1);

    cudaFuncSetAttribute(scan0_kernel, cudaFuncAttributeMaxDynamicSharedMemorySize, S0_SMEM);
    cudaFuncSetAttribute(scan1_kernel, cudaFuncAttributeMaxDynamicSharedMemorySize, S1_SMEM);

    reset_kernel<<<1, 256>>>();
    embed_kernel<<<(TT * BB * (DEMB / 4) + 255) / 256, 256>>>(x, emb, p_x0);

    dim3 gBig(G4H / 128, (TT * BB) / 128);   // (16, 256)
    gemm_mma<<<gBig, 256>>>(p_x0, wih0f, bih0f, p_xg0f, TT * BB, G4H, DEMB);
    gemm_mma<<<gBig, 256>>>(p_x0, wih0r, bih0r, p_xg0r, TT * BB, G4H, DEMB);

    scan0_kernel<<<128, 256, S0_SMEM>>>(p_xg0f, p_xg0r, whh0f, whh0r, bhh0f, bhh0r, p_h0);

    gemm_mma<<<gBig, 256>>>(p_h0, wih1f, bih1f, p_xg1f, TT * BB, G4H, 2 * HH);
    gemm_mma<<<dim3(G4H / 128, 1), 256>>>(
        p_h0 + (size_t)(TT - 1) * BB * 1024, wih1r, bih1r, p_xg1r, BB, G4H, 2 * HH);

    scan1_kernel<<<128, 128, S1_SMEM>>>(p_xg1f, whh1f, bhh1f, p_h1);

    hr_last_kernel<<<(BB * HH) / 256, 256>>>(p_xg1r, bhh1r, p_hr1);

    out_kernel<<<BB, 160>>>(p_h1 + BB * HH, p_hr1, wout, bout, out);
}

// round 4
// speedup vs baseline: 1.4994x; 1.2120x over previous
#include <cuda_runtime.h>
#include <cuda_bf16.h>
#include <math.h>
#include <cstdint>

#define TT 256
#define BB 128
#define HH 512
#define DEMB 256
#define PAD_IDX 29999
#define NCLS 5
#define G4H 2048  // 4*HH

__device__ __forceinline__ uint32_t smem_to_u32(const void* p) {
    uint32_t a;
    asm("{ .reg .u64 t; cvta.to.shared.u64 t, %1; cvt.u32.u64 %0, t; }" : "=r"(a) : "l"(p));
    return a;
}
#define CP_ASYNC16(dst, src) \
    asm volatile("cp.async.cg.shared.global [%0], [%1], 16;" :: "r"(dst), "l"(src))
#define CP_COMMIT  asm volatile("cp.async.commit_group;" ::: "memory")
#define CP_WAIT_1  asm volatile("cp.async.wait_group 1;" ::: "memory")
#define CP_WAIT_0  asm volatile("cp.async.wait_group 0;" ::: "memory")

// ========================= scratch (static, no allocs) =======================
__device__ float g_x0  [(size_t)TT * BB * DEMB];
__device__ float g_xg0f[(size_t)TT * BB * G4H];
__device__ float g_xg0r[(size_t)TT * BB * G4H];
__device__ float g_h0  [(size_t)TT * BB * 2 * HH];
__device__ float g_xg1f[(size_t)TT * BB * G4H];
__device__ float g_xg1r[(size_t)BB * G4H];
__device__ float g_h1  [2 * BB * HH];
__device__ float g_hr1 [BB * HH];
// h split buffers: [dir][parity][128][512] bf16
__device__ __nv_bfloat16 g_hsp0_hi[2 * 2 * BB * HH];
__device__ __nv_bfloat16 g_hsp0_lo[2 * 2 * BB * HH];
__device__ __nv_bfloat16 g_hsp1_hi[2 * BB * HH];
__device__ __nv_bfloat16 g_hsp1_lo[2 * BB * HH];
__device__ int g_bar0[2 * TT];
__device__ int g_bar1[TT];

__global__ void reset_kernel() {
    int i = blockIdx.x * blockDim.x + threadIdx.x;
    if (i < 2 * TT) g_bar0[i] = 0;
    if (i < TT)     g_bar1[i] = 0;
}

// ========================= embedding gather ==================================
__global__ void embed_kernel(const int* __restrict__ x,
                             const float* __restrict__ emb,
                             float* __restrict__ out) {
    int gid = blockIdx.x * blockDim.x + threadIdx.x;
    if (gid >= TT * BB * (DEMB / 4)) return;
    int i4  = gid & 63;
    int row = gid >> 6;
    int t = row / BB;
    int b = row - t * BB;
    int xi = x[b * TT + t];
    float4 v;
    if (xi == PAD_IDX) { v.x = v.y = v.z = v.w = 0.f; }
    else               { v = ((const float4*)emb)[(size_t)xi * 64 + i4]; }
    ((float4*)out)[gid] = v;
}

// ========================= mma primitives ====================================
__device__ __forceinline__ void ldsm4(uint32_t* r, uint32_t addr) {
    asm volatile("ldmatrix.sync.aligned.m8n8.x4.shared.b16 {%0,%1,%2,%3}, [%4];"
        : "=r"(r[0]), "=r"(r[1]), "=r"(r[2]), "=r"(r[3]) : "r"(addr));
}
__device__ __forceinline__ void mma_bf16(float* d, const uint32_t* a,
                                         uint32_t b0, uint32_t b1) {
    asm volatile("mma.sync.aligned.m16n8k16.row.col.f32.bf16.bf16.f32 "
        "{%0,%1,%2,%3}, {%4,%5,%6,%7}, {%8,%9}, {%0,%1,%2,%3};"
        : "+f"(d[0]), "+f"(d[1]), "+f"(d[2]), "+f"(d[3])
        : "r"(a[0]), "r"(a[1]), "r"(a[2]), "r"(a[3]), "r"(b0), "r"(b1));
}
__device__ __forceinline__ void split_store(uint32_t hi_addr, uint32_t lo_addr,
                                            float4 v) {
    uint32_t h01, h23;
    asm("cvt.rn.bf16x2.f32 %0, %1, %2;" : "=r"(h01) : "f"(v.y), "f"(v.x));
    asm("cvt.rn.bf16x2.f32 %0, %1, %2;" : "=r"(h23) : "f"(v.w), "f"(v.z));
    float f0 = __uint_as_float(h01 << 16);
    float f1 = __uint_as_float(h01 & 0xffff0000u);
    float f2 = __uint_as_float(h23 << 16);
    float f3 = __uint_as_float(h23 & 0xffff0000u);
    float r0 = v.x - f0, r1 = v.y - f1, r2 = v.z - f2, r3 = v.w - f3;
    uint32_t l01, l23;
    asm("cvt.rn.bf16x2.f32 %0, %1, %2;" : "=r"(l01) : "f"(r1), "f"(r0));
    asm("cvt.rn.bf16x2.f32 %0, %1, %2;" : "=r"(l23) : "f"(r3), "f"(r2));
    asm volatile("st.shared.v2.b32 [%0], {%1, %2};" :: "r"(hi_addr), "r"(h01), "r"(h23) : "memory");
    asm volatile("st.shared.v2.b32 [%0], {%1, %2};" :: "r"(lo_addr), "r"(l01), "r"(l23) : "memory");
}

// ========================= mma.sync bf16 split-3 GEMM (unchanged) ============
#define KC  32
#define LDH 40

__global__ __launch_bounds__(256) void gemm_mma(const float* __restrict__ A,
                                                const float* __restrict__ W,
                                                const float* __restrict__ bias,
                                                float* __restrict__ C,
                                                int M, int N, int K) {
    __shared__ __align__(16) __nv_bfloat16 smem[4 * 128 * LDH];
    const uint32_t sb = smem_to_u32(smem);
    const uint32_t AH = sb;
    const uint32_t AL = sb + 128 * LDH * 2;
    const uint32_t BH = sb + 2 * 128 * LDH * 2;
    const uint32_t BL = sb + 3 * 128 * LDH * 2;

    const int tid  = threadIdx.x;
    const int lane = tid & 31;
    const int wid  = tid >> 5;
    const int wm   = wid & 3;
    const int wn   = wid >> 2;
    const int bm   = blockIdx.y * 128;
    const int bn   = blockIdx.x * 128;

    float acc[2][8][4];
#pragma unroll
    for (int i = 0; i < 2; i++)
#pragma unroll
        for (int j = 0; j < 8; j++)
#pragma unroll
            for (int k = 0; k < 4; k++) acc[i][j][k] = 0.f;

    const uint32_t a_row = lane & 15;
    const uint32_t a_col = (lane >> 4) << 3;
    const uint32_t b_n   = (lane & 7) + ((lane >> 4) << 3);
    const uint32_t b_k   = ((lane >> 3) & 1) << 3;

    for (int kb = 0; kb < K; kb += KC) {
        __syncthreads();
#pragma unroll
        for (int i = 0; i < 4; i++) {
            int idx = tid + i * 256;
            int row = idx >> 3, c4 = idx & 7;
            float4 v = *(const float4*)(A + (size_t)(bm + row) * K + kb + c4 * 4);
            uint32_t off = (row * LDH + c4 * 4) * 2;
            split_store(AH + off, AL + off, v);
        }
#pragma unroll
        for (int i = 0; i < 4; i++) {
            int idx = tid + i * 256;
            int row = idx >> 3, c4 = idx & 7;
            float4 v = *(const float4*)(W + (size_t)(bn + row) * K + kb + c4 * 4);
            uint32_t off = (row * LDH + c4 * 4) * 2;
            split_store(BH + off, BL + off, v);
        }
        __syncthreads();

#pragma unroll
        for (int ks = 0; ks < KC; ks += 16) {
            uint32_t ah[2][4], al[2][4];
#pragma unroll
            for (int ma = 0; ma < 2; ma++) {
                uint32_t off = ((wm * 32 + ma * 16 + a_row) * LDH + ks + a_col) * 2;
                ldsm4(ah[ma], AH + off);
                ldsm4(al[ma], AL + off);
            }
#pragma unroll
            for (int bg = 0; bg < 4; bg++) {
                uint32_t boff = ((wn * 64 + bg * 16 + b_n) * LDH + ks + b_k) * 2;
                uint32_t bh[4], bl[4];
                ldsm4(bh, BH + boff);
                ldsm4(bl, BL + boff);
#pragma unroll
                for (int ma = 0; ma < 2; ma++) {
#pragma unroll
                    for (int na = 0; na < 2; na++) {
                        float* d = acc[ma][bg * 2 + na];
                        mma_bf16(d, ah[ma], bh[na * 2], bh[na * 2 + 1]);
                        mma_bf16(d, ah[ma], bl[na * 2], bl[na * 2 + 1]);
                        mma_bf16(d, al[ma], bh[na * 2], bh[na * 2 + 1]);
                    }
                }
            }
        }
    }

#pragma unroll
    for (int ma = 0; ma < 2; ma++) {
        int row0 = bm + wm * 32 + ma * 16 + (lane >> 2);
#pragma unroll
        for (int na = 0; na < 8; na++) {
            int col = bn + wn * 64 + na * 8 + (lane & 3) * 2;
            float b0 = bias[col], b1 = bias[col + 1];
            float2 v0 = make_float2(acc[ma][na][0] + b0, acc[ma][na][1] + b1);
            float2 v1 = make_float2(acc[ma][na][2] + b0, acc[ma][na][3] + b1);
            *(float2*)(C + (size_t)row0 * N + col) = v0;
            *(float2*)(C + (size_t)(row0 + 8) * N + col) = v1;
        }
    }
}

__device__ __forceinline__ float sigmoidf_(float v) { return 1.f / (1.f + expf(-v)); }

// ========================= tensor-core LSTM scan =============================
// CTA owns 8 hidden units (32 gate rows, ordered n = gate*8 + unit) x all 128
// batches. W slice (hi/lo bf16) persistent in smem; h staged per 64-K chunk
// from pre-split global bf16 buffers via cp.async.cg, double-buffered.
// Layer0: grid 128 (64 per dir). Layer1: grid 64 (fwd only).
#define W_STRIDE 520                 // halves; 1040B = 65*16B -> conflict-free
#define A_STRIDE 72                  // halves; 144B = 9*16B
#define W_BYTES (32 * W_STRIDE * 2)  // 33280
#define A_BYTES (BB * A_STRIDE * 2)  // 18432
#define SCAN_SMEM (2 * W_BYTES + 4 * A_BYTES)  // 140288

__device__ __forceinline__ void stage_chunk(uint32_t dbase,
                                            const __nv_bfloat16* shi,
                                            const __nv_bfloat16* slo,
                                            int kb, int tid) {
#pragma unroll
    for (int i = 0; i < 8; i++) {
        int e = tid + i * 256;
        int split = e >> 10, rem = e & 1023;
        int row = rem >> 3, seg = rem & 7;
        const __nv_bfloat16* src = (split ? slo : shi) + row * HH + kb + seg * 8;
        uint32_t dst = dbase + split * A_BYTES + (row * A_STRIDE + seg * 8) * 2;
        CP_ASYNC16(dst, src);
    }
}

template<bool L0>
__global__ __launch_bounds__(256, 1) void scan_mma(
    const float* __restrict__ xgf, const float* __restrict__ xgr,
    const float* __restrict__ whhf, const float* __restrict__ whhr,
    const float* __restrict__ bhhf, const float* __restrict__ bhhr,
    __nv_bfloat16* __restrict__ hsp_hi, __nv_bfloat16* __restrict__ hsp_lo,
    float* __restrict__ hout, int* __restrict__ bar) {
    extern __shared__ __align__(16) char smem[];
    const uint32_t sb  = smem_to_u32(smem);
    const uint32_t WHI = sb;
    const uint32_t WLO = sb + W_BYTES;
    const uint32_t ABASE = sb + 2 * W_BYTES;     // [buf][split]

    const int tid  = threadIdx.x;
    const int lane = tid & 31;
    const int wm   = tid >> 5;                   // 8 M-tiles of 16 batches
    const int dir  = L0 ? (int)(blockIdx.x >> 6) : 0;
    const int slice = L0 ? (int)(blockIdx.x & 63) : (int)blockIdx.x;
    const int j0 = slice * 8;

    const float* whh = (L0 && dir) ? whhr : whhf;
    const float* bhh = (L0 && dir) ? bhhr : bhhf;
    const float* xg  = (L0 && dir) ? xgr  : xgf;
    int* barp = bar + dir * TT;
    __nv_bfloat16* hhi = hsp_hi + (size_t)dir * 2 * BB * HH;
    __nv_bfloat16* hlo = hsp_lo + (size_t)dir * 2 * BB * HH;

    // load W slice into smem (hi/lo): rows n = g*8+u <- whh[g*512 + j0 + u]
#pragma unroll
    for (int i = 0; i < 16; i++) {
        int idx = tid + i * 256;                 // 0..4095
        int n = idx >> 7, c4 = idx & 127;
        int grow = (n >> 3) * 512 + j0 + (n & 7);
        float4 v = *(const float4*)(whh + (size_t)grow * 512 + c4 * 4);
        uint32_t off = (n * W_STRIDE + c4 * 4) * 2;
        split_store(WHI + off, WLO + off, v);
    }
    __syncthreads();

    const uint32_t a_row = lane & 15;
    const uint32_t a_col = (lane >> 4) << 3;
    const uint32_t b_n   = (lane & 7) + ((lane >> 4) << 3);
    const uint32_t b_k   = ((lane >> 3) & 1) << 3;
    const int r = lane >> 2;
    const int u = (lane & 3) * 2;

    float bias[4][2];
#pragma unroll
    for (int g = 0; g < 4; g++) {
        bias[g][0] = bhh[g * 512 + j0 + u];
        bias[g][1] = bhh[g * 512 + j0 + u + 1];
    }

    float c[4] = {0.f, 0.f, 0.f, 0.f};

    for (int step = 0; step < TT; step++) {
        const int t = (L0 && dir) ? (TT - 1 - step) : step;

        // prefetch xg (input-gate preactivations, fp32)
        float2 xv[4][2];
        {
            const float* xp = xg + ((size_t)(t * BB + wm * 16 + r)) * G4H + j0 + u;
#pragma unroll
            for (int g = 0; g < 4; g++) {
#pragma unroll
                for (int rp = 0; rp < 2; rp++)
                    xv[g][rp] = *(const float2*)(xp + (size_t)rp * 8 * G4H + g * 512);
            }
        }

        float acc[4][4];
#pragma unroll
        for (int g = 0; g < 4; g++)
#pragma unroll
            for (int k = 0; k < 4; k++) acc[g][k] = 0.f;

        if (step > 0) {
            const int rpar = (step - 1) & 1;
            const __nv_bfloat16* shi = hhi + (size_t)rpar * BB * HH;
            const __nv_bfloat16* slo = hlo + (size_t)rpar * BB * HH;

            stage_chunk(ABASE, shi, slo, 0, tid);
            CP_COMMIT;
            for (int ch = 0; ch < 8; ch++) {
                if (ch < 7) {
                    stage_chunk(ABASE + ((ch + 1) & 1) * 2 * A_BYTES, shi, slo,
                                (ch + 1) * 64, tid);
                    CP_COMMIT;
                    CP_WAIT_1;
                } else {
                    CP_WAIT_0;
                }
                __syncthreads();
                const uint32_t AH = ABASE + (ch & 1) * 2 * A_BYTES;
                const uint32_t AL = AH + A_BYTES;
#pragma unroll
                for (int kk = 0; kk < 64; kk += 16) {
                    uint32_t aoff = ((wm * 16 + a_row) * A_STRIDE + kk + a_col) * 2;
                    uint32_t ah[4], al[4];
                    ldsm4(ah, AH + aoff);
                    ldsm4(al, AL + aoff);
                    int kg = ch * 64 + kk;
                    uint32_t bh0[4], bh1[4], bl0[4], bl1[4];
                    ldsm4(bh0, WHI + ((0  + b_n) * W_STRIDE + kg + b_k) * 2);
                    ldsm4(bh1, WHI + ((16 + b_n) * W_STRIDE + kg + b_k) * 2);
                    ldsm4(bl0, WLO + ((0  + b_n) * W_STRIDE + kg + b_k) * 2);
                    ldsm4(bl1, WLO + ((16 + b_n) * W_STRIDE + kg + b_k) * 2);
                    mma_bf16(acc[0], ah, bh0[0], bh0[1]);
                    mma_bf16(acc[0], ah, bl0[0], bl0[1]);
                    mma_bf16(acc[0], al, bh0[0], bh0[1]);
                    mma_bf16(acc[1], ah, bh0[2], bh0[3]);
                    mma_bf16(acc[1], ah, bl0[2], bl0[3]);
                    mma_bf16(acc[1], al, bh0[2], bh0[3]);
                    mma_bf16(acc[2], ah, bh1[0], bh1[1]);
                    mma_bf16(acc[2], ah, bl1[0], bl1[1]);
                    mma_bf16(acc[2], al, bh1[0], bh1[1]);
                    mma_bf16(acc[3], ah, bh1[2], bh1[3]);
                    mma_bf16(acc[3], ah, bl1[2], bl1[3]);
                    mma_bf16(acc[3], al, bh1[2], bh1[3]);
                }
                __syncthreads();
            }
        }

        // nonlinearity (fully register-local) + h publication
        const int wpar = step & 1;
        __nv_bfloat16* dhi = hhi + (size_t)wpar * BB * HH;
        __nv_bfloat16* dlo = hlo + (size_t)wpar * BB * HH;
#pragma unroll
        for (int rp = 0; rp < 2; rp++) {
            const int b = wm * 16 + r + rp * 8;
            float hv2[2];
#pragma unroll
            for (int cc = 0; cc < 2; cc++) {
                const int k = rp * 2 + cc;
                float xi_ = cc ? xv[0][rp].y : xv[0][rp].x;
                float xf_ = cc ? xv[1][rp].y : xv[1][rp].x;
                float xg_ = cc ? xv[2][rp].y : xv[2][rp].x;
                float xo_ = cc ? xv[3][rp].y : xv[3][rp].x;
                float gi = acc[0][k] + xi_ + bias[0][cc];
                float gf = acc[1][k] + xf_ + bias[1][cc];
                float gg = acc[2][k] + xg_ + bias[2][cc];
                float go = acc[3][k] + xo_ + bias[3][cc];
                float cv = sigmoidf_(gf) * c[k] + sigmoidf_(gi) * tanhf(gg);
                c[k] = cv;
                hv2[cc] = sigmoidf_(go) * tanhf(cv);
            }
            // fp32 h for downstream consumers
            if (L0) {
                *(float2*)(hout + ((size_t)(t * BB + b)) * 1024 + dir * 512 + j0 + u) =
                    make_float2(hv2[0], hv2[1]);
            } else {
                *(float2*)(hout + (size_t)wpar * BB * HH + (size_t)b * HH + j0 + u) =
                    make_float2(hv2[0], hv2[1]);
            }
            // bf16 hi/lo split for next-step MMA
            uint32_t hi2;
            asm("cvt.rn.bf16x2.f32 %0, %1, %2;" : "=r"(hi2) : "f"(hv2[1]), "f"(hv2[0]));
            float f0 = __uint_as_float(hi2 << 16);
            float f1 = __uint_as_float(hi2 & 0xffff0000u);
            float r0 = hv2[0] - f0, r1 = hv2[1] - f1;
            uint32_t lo2;
            asm("cvt.rn.bf16x2.f32 %0, %1, %2;" : "=r"(lo2) : "f"(r1), "f"(r0));
            *(uint32_t*)((char*)dhi + ((size_t)b * HH + j0 + u) * 2) = hi2;
            *(uint32_t*)((char*)dlo + ((size_t)b * HH + j0 + u) * 2) = lo2;
        }

        // per-direction global step barrier (64 CTAs)
        if (step < TT - 1) {
            __threadfence();
            __syncthreads();
            if (tid == 0) {
                atomicAdd(barp + step, 1);
                while (((volatile int*)barp)[step] < 64) {}
            }
            __syncthreads();
        }
    }
}

// ========================= layer-1 reverse at t = T-1 ========================
__global__ void hr_last_kernel(const float* __restrict__ xg,
                               const float* __restrict__ bhh,
                               float* __restrict__ hr) {
    int idx = blockIdx.x * blockDim.x + threadIdx.x;
    if (idx >= BB * HH) return;
    int b = idx >> 9, j = idx & 511;
    float gi = xg[(size_t)b * G4H + j]        + bhh[j];
    float gg = xg[(size_t)b * G4H + 1024 + j] + bhh[1024 + j];
    float go = xg[(size_t)b * G4H + 1536 + j] + bhh[1536 + j];
    float cv = sigmoidf_(gi) * tanhf(gg);
    hr[idx] = sigmoidf_(go) * tanhf(cv);
}

// ========================= final projection ==================================
__global__ void out_kernel(const float* __restrict__ hf, const float* __restrict__ hr,
                           const float* __restrict__ wout, const float* __restrict__ bout,
                           float* __restrict__ out) {
    int b = blockIdx.x;
    int warp = threadIdx.x >> 5;
    int lane = threadIdx.x & 31;
    float s = 0.f;
    for (int k = lane; k < 512; k += 32) s += hf[(size_t)b * HH + k] * wout[warp * 1024 + k];
    for (int k = lane; k < 512; k += 32) s += hr[(size_t)b * HH + k] * wout[warp * 1024 + 512 + k];
#pragma unroll
    for (int off = 16; off; off >>= 1) s += __shfl_xor_sync(0xffffffffu, s, off);
    if (lane == 0) out[b * NCLS + warp] = s + bout[warp];
}

// ========================= host launch =======================================
extern "C" void kernel_launch(void* const* d_in, const int* in_sizes, int n_in,
                              void* d_out, int out_size) {
    const int*   x     = (const int*)  d_in[0];
    const float* emb   = (const float*)d_in[1];
    const float* wih0f = (const float*)d_in[2];
    const float* whh0f = (const float*)d_in[3];
    const float* bih0f = (const float*)d_in[4];
    const float* bhh0f = (const float*)d_in[5];
    const float* wih0r = (const float*)d_in[6];
    const float* whh0r = (const float*)d_in[7];
    const float* bih0r = (const float*)d_in[8];
    const float* bhh0r = (const float*)d_in[9];
    const float* wih1f = (const float*)d_in[10];
    const float* whh1f = (const float*)d_in[11];
    const float* bih1f = (const float*)d_in[12];
    const float* bhh1f = (const float*)d_in[13];
    const float* wih1r = (const float*)d_in[14];
    const float* whh1r = (const float*)d_in[15]; (void)whh1r;
    const float* bih1r = (const float*)d_in[16];
    const float* bhh1r = (const float*)d_in[17];
    const float* wout  = (const float*)d_in[18];
    const float* bout  = (const float*)d_in[19];
    float* out = (float*)d_out;

    float *p_x0, *p_xg0f, *p_xg0r, *p_h0, *p_xg1f, *p_xg1r, *p_h1, *p_hr1;
    __nv_bfloat16 *p_h0hi, *p_h0lo, *p_h1hi, *p_h1lo;
    int *p_bar0, *p_bar1;
    cudaGetSymbolAddress((void**)&p_x0,   g_x0);
    cudaGetSymbolAddress((void**)&p_xg0f, g_xg0f);
    cudaGetSymbolAddress((void**)&p_xg0r, g_xg0r);
    cudaGetSymbolAddress((void**)&p_h0,   g_h0);
    cudaGetSymbolAddress((void**)&p_xg1f, g_xg1f);
    cudaGetSymbolAddress((void**)&p_xg1r, g_xg1r);
    cudaGetSymbolAddress((void**)&p_h1,   g_h1);
    cudaGetSymbolAddress((void**)&p_hr1,  g_hr1);
    cudaGetSymbolAddress((void**)&p_h0hi, g_hsp0_hi);
    cudaGetSymbolAddress((void**)&p_h0lo, g_hsp0_lo);
    cudaGetSymbolAddress((void**)&p_h1hi, g_hsp1_hi);
    cudaGetSymbolAddress((void**)&p_h1lo, g_hsp1_lo);
    cudaGetSymbolAddress((void**)&p_bar0, g_bar0);
    cudaGetSymbolAddress((void**)&p_bar1, g_bar1);

    cudaFuncSetAttribute(scan_mma<true>,  cudaFuncAttributeMaxDynamicSharedMemorySize, SCAN_SMEM);
    cudaFuncSetAttribute(scan_mma<false>, cudaFuncAttributeMaxDynamicSharedMemorySize, SCAN_SMEM);

    reset_kernel<<<2, 512>>>();
    embed_kernel<<<(TT * BB * (DEMB / 4) + 255) / 256, 256>>>(x, emb, p_x0);

    dim3 gBig(G4H / 128, (TT * BB) / 128);   // (16, 256)
    gemm_mma<<<gBig, 256>>>(p_x0, wih0f, bih0f, p_xg0f, TT * BB, G4H, DEMB);
    gemm_mma<<<gBig, 256>>>(p_x0, wih0r, bih0r, p_xg0r, TT * BB, G4H, DEMB);

    scan_mma<true><<<128, 256, SCAN_SMEM>>>(p_xg0f, p_xg0r, whh0f, whh0r,
                                            bhh0f, bhh0r, p_h0hi, p_h0lo,
                                            p_h0, p_bar0);

    gemm_mma<<<gBig, 256>>>(p_h0, wih1f, bih1f, p_xg1f, TT * BB, G4H, 2 * HH);
    gemm_mma<<<dim3(G4H / 128, 1), 256>>>(
        p_h0 + (size_t)(TT - 1) * BB * 1024, wih1r, bih1r, p_xg1r, BB, G4H, 2 * HH);

    scan_mma<false><<<64, 256, SCAN_SMEM>>>(p_xg1f, p_xg1f, whh1f, whh1f,
                                            bhh1f, bhh1f, p_h1hi, p_h1lo,
                                            p_h1, p_bar1);

    hr_last_kernel<<<(BB * HH) / 256, 256>>>(p_xg1r, bhh1r, p_hr1);

    // (T-1) odd -> final forward state in ping-pong buffer 1
    out_kernel<<<BB, 160>>>(p_h1 + BB * HH, p_hr1, wout, bout, out);
}

// round 5
// speedup vs baseline: 3.5440x; 2.3636x over previous
#include <cuda_runtime.h>
#include <cuda_fp16.h>
#include <math.h>
#include <cstdint>

#define TT 256
#define BB 128
#define HH 512
#define DEMB 256
#define PAD_IDX 29999
#define NCLS 5
#define G4H 2048  // 4*HH

__device__ __forceinline__ uint32_t smem_to_u32(const void* p) {
    uint32_t a;
    asm("{ .reg .u64 t; cvta.to.shared.u64 t, %1; cvt.u32.u64 %0, t; }" : "=r"(a) : "l"(p));
    return a;
}
#define CP_ASYNC16(dst, src) \
    asm volatile("cp.async.cg.shared.global [%0], [%1], 16;" :: "r"(dst), "l"(src))
#define CP_COMMIT  asm volatile("cp.async.commit_group;" ::: "memory")
#define CP_WAIT_1  asm volatile("cp.async.wait_group 1;" ::: "memory")
#define CP_WAIT_0  asm volatile("cp.async.wait_group 0;" ::: "memory")

// ========================= scratch (static, no allocs) =======================
__device__ float g_x0  [(size_t)TT * BB * DEMB];
__device__ float g_xg0f[(size_t)TT * BB * G4H];
__device__ float g_xg0r[(size_t)TT * BB * G4H];
__device__ float g_h0  [(size_t)TT * BB * 2 * HH];
__device__ float g_xg1f[(size_t)TT * BB * G4H];
__device__ float g_xg1r[(size_t)BB * G4H];
__device__ float g_h1f [BB * HH];          // final layer1 fwd state (t = T-1)
__device__ float g_hr1 [BB * HH];
__device__ __half g_hf0[2 * 2 * BB * HH];  // layer0 h fp16 [dir][parity][b][512]
__device__ __half g_hf1[2 * BB * HH];      // layer1 h fp16 [parity][b][512]
__device__ int g_bar0[2 * TT];
__device__ int g_bar1[2 * TT];

__global__ void reset_kernel() {
    int i = threadIdx.x;
    if (i < 2 * TT) { g_bar0[i] = 0; g_bar1[i] = 0; }
}

// ========================= embedding gather ==================================
__global__ void embed_kernel(const int* __restrict__ x,
                             const float* __restrict__ emb,
                             float* __restrict__ out) {
    int gid = blockIdx.x * blockDim.x + threadIdx.x;
    if (gid >= TT * BB * (DEMB / 4)) return;
    int i4  = gid & 63;
    int row = gid >> 6;
    int t = row / BB;
    int b = row - t * BB;
    int xi = x[b * TT + t];
    float4 v;
    if (xi == PAD_IDX) { v.x = v.y = v.z = v.w = 0.f; }
    else               { v = ((const float4*)emb)[(size_t)xi * 64 + i4]; }
    ((float4*)out)[gid] = v;
}

// ========================= mma primitives ====================================
__device__ __forceinline__ void ldsm4(uint32_t* r, uint32_t addr) {
    asm volatile("ldmatrix.sync.aligned.m8n8.x4.shared.b16 {%0,%1,%2,%3}, [%4];"
        : "=r"(r[0]), "=r"(r[1]), "=r"(r[2]), "=r"(r[3]) : "r"(addr));
}
__device__ __forceinline__ void mma_f16(float* d, const uint32_t* a,
                                        uint32_t b0, uint32_t b1) {
    asm volatile("mma.sync.aligned.m16n8k16.row.col.f32.f16.f16.f32 "
        "{%0,%1,%2,%3}, {%4,%5,%6,%7}, {%8,%9}, {%0,%1,%2,%3};"
        : "+f"(d[0]), "+f"(d[1]), "+f"(d[2]), "+f"(d[3])
        : "r"(a[0]), "r"(a[1]), "r"(a[2]), "r"(a[3]), "r"(b0), "r"(b1));
}
__device__ __forceinline__ uint32_t pack_h2(float a, float b) {
    __half2 h = __floats2half2_rn(a, b);
    return *(uint32_t*)&h;
}
// W: fp16 hi + lo residual
__device__ __forceinline__ void splitw_store(uint32_t hiA, uint32_t loA, float4 v) {
    __half h0 = __float2half_rn(v.x), h1 = __float2half_rn(v.y);
    __half h2 = __float2half_rn(v.z), h3 = __float2half_rn(v.w);
    float r0 = v.x - __half2float(h0), r1 = v.y - __half2float(h1);
    float r2 = v.z - __half2float(h2), r3 = v.w - __half2float(h3);
    uint32_t hp0 = pack_h2(__half2float(h0), __half2float(h1));
    uint32_t hp1 = pack_h2(__half2float(h2), __half2float(h3));
    uint32_t lp0 = pack_h2(r0, r1);
    uint32_t lp1 = pack_h2(r2, r3);
    asm volatile("st.shared.v2.b32 [%0], {%1, %2};" :: "r"(hiA), "r"(hp0), "r"(hp1) : "memory");
    asm volatile("st.shared.v2.b32 [%0], {%1, %2};" :: "r"(loA), "r"(lp0), "r"(lp1) : "memory");
}
__device__ __forceinline__ void a_store(uint32_t dst, float4 v) {
    uint32_t p0 = pack_h2(v.x, v.y), p1 = pack_h2(v.z, v.w);
    asm volatile("st.shared.v2.b32 [%0], {%1, %2};" :: "r"(dst), "r"(p0), "r"(p1) : "memory");
}

// ========================= fp16 2-term GEMM: C = A*W^T + bias ================
#define KC  32
#define LDH 40

__global__ __launch_bounds__(256) void gemm_mma(const float* __restrict__ A,
                                                const float* __restrict__ W,
                                                const float* __restrict__ bias,
                                                float* __restrict__ C,
                                                int M, int N, int K) {
    __shared__ __align__(16) __half smem[3 * 128 * LDH];
    const uint32_t sb = smem_to_u32(smem);
    const uint32_t AH = sb;
    const uint32_t BH = sb + 128 * LDH * 2;
    const uint32_t BL = sb + 2 * 128 * LDH * 2;

    const int tid  = threadIdx.x;
    const int lane = tid & 31;
    const int wid  = tid >> 5;
    const int wm   = wid & 3;
    const int wn   = wid >> 2;
    const int bm   = blockIdx.y * 128;
    const int bn   = blockIdx.x * 128;

    float acc[2][8][4];
#pragma unroll
    for (int i = 0; i < 2; i++)
#pragma unroll
        for (int j = 0; j < 8; j++)
#pragma unroll
            for (int k = 0; k < 4; k++) acc[i][j][k] = 0.f;

    const uint32_t a_row = lane & 15;
    const uint32_t a_col = (lane >> 4) << 3;
    const uint32_t b_n   = (lane & 7) + ((lane >> 4) << 3);
    const uint32_t b_k   = ((lane >> 3) & 1) << 3;

    for (int kb = 0; kb < K; kb += KC) {
        __syncthreads();
#pragma unroll
        for (int i = 0; i < 4; i++) {
            int idx = tid + i * 256;
            int row = idx >> 3, c4 = idx & 7;
            float4 v = *(const float4*)(A + (size_t)(bm + row) * K + kb + c4 * 4);
            a_store(AH + (row * LDH + c4 * 4) * 2, v);
        }
#pragma unroll
        for (int i = 0; i < 4; i++) {
            int idx = tid + i * 256;
            int row = idx >> 3, c4 = idx & 7;
            float4 v = *(const float4*)(W + (size_t)(bn + row) * K + kb + c4 * 4);
            uint32_t off = (row * LDH + c4 * 4) * 2;
            splitw_store(BH + off, BL + off, v);
        }
        __syncthreads();

#pragma unroll
        for (int ks = 0; ks < KC; ks += 16) {
            uint32_t ah[2][4];
#pragma unroll
            for (int ma = 0; ma < 2; ma++)
                ldsm4(ah[ma], AH + ((wm * 32 + ma * 16 + a_row) * LDH + ks + a_col) * 2);
#pragma unroll
            for (int bg = 0; bg < 4; bg++) {
                uint32_t boff = ((wn * 64 + bg * 16 + b_n) * LDH + ks + b_k) * 2;
                uint32_t bh[4], bl[4];
                ldsm4(bh, BH + boff);
                ldsm4(bl, BL + boff);
#pragma unroll
                for (int ma = 0; ma < 2; ma++) {
#pragma unroll
                    for (int na = 0; na < 2; na++) {
                        float* d = acc[ma][bg * 2 + na];
                        mma_f16(d, ah[ma], bh[na * 2], bh[na * 2 + 1]);
                        mma_f16(d, ah[ma], bl[na * 2], bl[na * 2 + 1]);
                    }
                }
            }
        }
    }

#pragma unroll
    for (int ma = 0; ma < 2; ma++) {
        int row0 = bm + wm * 32 + ma * 16 + (lane >> 2);
#pragma unroll
        for (int na = 0; na < 8; na++) {
            int col = bn + wn * 64 + na * 8 + (lane & 3) * 2;
            float b0 = bias[col], b1 = bias[col + 1];
            float2 v0 = make_float2(acc[ma][na][0] + b0, acc[ma][na][1] + b1);
            float2 v1 = make_float2(acc[ma][na][2] + b0, acc[ma][na][3] + b1);
            *(float2*)(C + (size_t)row0 * N + col) = v0;
            *(float2*)(C + (size_t)(row0 + 8) * N + col) = v1;
        }
    }
}

__device__ __forceinline__ float sigmoidf_(float v) { return 1.f / (1.f + expf(-v)); }

// ========================= tensor-core LSTM scan (fp16) ======================
// L0: 128 CTAs = 2 dirs x 64 unit-slices(8u); CTA: M=128 batches, N=32, K=512.
//     8 warps = 8 m-tiles, full K each.
// L1: 128 CTAs = 2 batch-halves x 64 unit-slices; CTA: M=64, N=32, K=512.
//     8 warps = 4 m-tiles x 2 K-halves, smem reduction.
#define W_STR 520
#define A_STR 264
#define W_SPL_BYTES (32 * W_STR * 2)    // 33280
#define SCAN_W_BYTES (2 * W_SPL_BYTES)  // 66560
#define SCAN0_SMEM (SCAN_W_BYTES + 2 * 128 * A_STR * 2)  // 201728
#define SCAN1_SMEM (SCAN_W_BYTES + 2 * 64 * A_STR * 2)   // 134144

template<int MC>
__device__ __forceinline__ void stage_chunk(uint32_t dst, const __half* hs,
                                            int bbase, int kb, int tid) {
#pragma unroll
    for (int i = 0; i < MC / 8; i++) {
        int e = tid + i * 256;
        int row = e >> 5, seg = e & 31;
        const __half* src = hs + (size_t)(bbase + row) * HH + kb + seg * 8;
        CP_ASYNC16(dst + (row * A_STR + seg * 8) * 2, src);
    }
}

__device__ __forceinline__ void mma_chunk(uint32_t AB, uint32_t WHI, uint32_t WLO,
                                          int mrow, int kg0,
                                          uint32_t a_row, uint32_t a_col,
                                          uint32_t b_n, uint32_t b_k,
                                          float acc[4][4]) {
#pragma unroll
    for (int kk = 0; kk < 16; kk++) {
        uint32_t a[4];
        ldsm4(a, AB + ((mrow + a_row) * A_STR + kk * 16 + a_col) * 2);
        int kg = kg0 + kk * 16;
        uint32_t bh0[4], bh1[4], bl0[4], bl1[4];
        ldsm4(bh0, WHI + (b_n * W_STR + kg + b_k) * 2);
        ldsm4(bh1, WHI + ((16 + b_n) * W_STR + kg + b_k) * 2);
        ldsm4(bl0, WLO + (b_n * W_STR + kg + b_k) * 2);
        ldsm4(bl1, WLO + ((16 + b_n) * W_STR + kg + b_k) * 2);
        mma_f16(acc[0], a, bh0[0], bh0[1]);
        mma_f16(acc[0], a, bl0[0], bl0[1]);
        mma_f16(acc[1], a, bh0[2], bh0[3]);
        mma_f16(acc[1], a, bl0[2], bl0[3]);
        mma_f16(acc[2], a, bh1[0], bh1[1]);
        mma_f16(acc[2], a, bl1[0], bl1[1]);
        mma_f16(acc[3], a, bh1[2], bh1[3]);
        mma_f16(acc[3], a, bl1[2], bl1[3]);
    }
}

template<bool L0>
__global__ __launch_bounds__(256, 1) void scan_mma(
    const float* __restrict__ xgf, const float* __restrict__ xgr,
    const float* __restrict__ whhf, const float* __restrict__ whhr,
    const float* __restrict__ bhhf, const float* __restrict__ bhhr,
    __half* __restrict__ hrec, float* __restrict__ hout,
    int* __restrict__ bar) {
    constexpr int MC = L0 ? 128 : 64;
    constexpr int ASZ = MC * A_STR * 2;
    extern __shared__ __align__(16) char smem[];
    const uint32_t sb  = smem_to_u32(smem);
    const uint32_t WHI = sb, WLO = sb + W_SPL_BYTES;
    const uint32_t AB0 = sb + SCAN_W_BYTES, AB1 = AB0 + ASZ;

    const int tid = threadIdx.x, lane = tid & 31, wid = tid >> 5;
    const int grp   = blockIdx.x >> 6;   // L0: dir; L1: batch half
    const int slice = blockIdx.x & 63;
    const int j0    = slice * 8;
    const int bbase = L0 ? 0 : grp * 64;

    const float* whh = (L0 && grp) ? whhr : whhf;
    const float* bhh = (L0 && grp) ? bhhr : bhhf;
    const float* xg  = (L0 && grp) ? xgr  : xgf;
    int* barp = bar + grp * TT;
    __half* hbuf = hrec + (L0 ? (size_t)grp * 2 * BB * HH : 0);

    // W slice -> smem hi/lo fp16: rows n = g*8+u <- whh[g*512 + j0 + u]
#pragma unroll
    for (int i = 0; i < 16; i++) {
        int idx = tid + i * 256;             // 0..4095 float4
        int n = idx >> 7, c4 = idx & 127;
        int grow = (n >> 3) * 512 + j0 + (n & 7);
        float4 v = *(const float4*)(whh + (size_t)grow * 512 + c4 * 4);
        uint32_t off = (n * W_STR + c4 * 4) * 2;
        splitw_store(WHI + off, WLO + off, v);
    }
    __syncthreads();

    const uint32_t a_row = lane & 15;
    const uint32_t a_col = (lane >> 4) << 3;
    const uint32_t b_n   = (lane & 7) + ((lane >> 4) << 3);
    const uint32_t b_k   = ((lane >> 3) & 1) << 3;
    const int r = lane >> 2;
    const int u = (lane & 3) * 2;
    const int wm = L0 ? wid : (wid & 3);
    const int mrow = wm * 16;
    const bool owner = L0 || (wid < 4);

    float bias[4][2];
#pragma unroll
    for (int g = 0; g < 4; g++) {
        bias[g][0] = bhh[g * 512 + j0 + u];
        bias[g][1] = bhh[g * 512 + j0 + u + 1];
    }
    float c[4] = {0.f, 0.f, 0.f, 0.f};

    for (int step = 0; step < TT; step++) {
        const int t = (L0 && grp) ? (TT - 1 - step) : step;

        float2 xv[4][2];
        if (owner) {
            const float* xp = xg + ((size_t)(t * BB + bbase + mrow + r)) * G4H + j0 + u;
#pragma unroll
            for (int g = 0; g < 4; g++)
#pragma unroll
                for (int rp = 0; rp < 2; rp++)
                    xv[g][rp] = *(const float2*)(xp + (size_t)rp * 8 * G4H + g * 512);
        }

        float acc[4][4];
#pragma unroll
        for (int g = 0; g < 4; g++)
#pragma unroll
            for (int k = 0; k < 4; k++) acc[g][k] = 0.f;

        if (step > 0) {
            const int rpar = (step - 1) & 1;
            const __half* hs = hbuf + (size_t)rpar * BB * HH;
            stage_chunk<MC>(AB0, hs, bbase, 0, tid);   CP_COMMIT;
            stage_chunk<MC>(AB1, hs, bbase, 256, tid); CP_COMMIT;
            if (L0) {
                CP_WAIT_1;
                __syncthreads();
                mma_chunk(AB0, WHI, WLO, mrow, 0, a_row, a_col, b_n, b_k, acc);
                CP_WAIT_0;
                __syncthreads();
                mma_chunk(AB1, WHI, WLO, mrow, 256, a_row, a_col, b_n, b_k, acc);
            } else {
                CP_WAIT_0;
                __syncthreads();
                const int ks = wid >> 2;
                mma_chunk(ks ? AB1 : AB0, WHI, WLO, mrow, ks * 256,
                          a_row, a_col, b_n, b_k, acc);
            }
        }

        if (!L0) {
            // K-split reduction through smem (reuse AB0 after all reads done)
            __syncthreads();
            if (wid >= 4) {
                uint32_t base = AB0 + ((wid - 4) * 32 + lane) * 4;
#pragma unroll
                for (int f = 0; f < 16; f++)
                    *(float*)(smem + (base - sb) + f * 512) = acc[f >> 2][f & 3];
            }
            __syncthreads();
            if (wid < 4) {
                uint32_t base = AB0 + (wid * 32 + lane) * 4;
#pragma unroll
                for (int f = 0; f < 16; f++)
                    acc[f >> 2][f & 3] += *(float*)(smem + (base - sb) + f * 512);
            }
        }

        if (owner) {
            const int wpar = step & 1;
            __half* dh = hbuf + (size_t)wpar * BB * HH;
#pragma unroll
            for (int rp = 0; rp < 2; rp++) {
                const int b = bbase + mrow + r + rp * 8;
                float hv2[2];
#pragma unroll
                for (int cc = 0; cc < 2; cc++) {
                    const int k = rp * 2 + cc;
                    float xi_ = cc ? xv[0][rp].y : xv[0][rp].x;
                    float xf_ = cc ? xv[1][rp].y : xv[1][rp].x;
                    float xg_ = cc ? xv[2][rp].y : xv[2][rp].x;
                    float xo_ = cc ? xv[3][rp].y : xv[3][rp].x;
                    float gi = acc[0][k] + xi_ + bias[0][cc];
                    float gf = acc[1][k] + xf_ + bias[1][cc];
                    float gg = acc[2][k] + xg_ + bias[2][cc];
                    float go = acc[3][k] + xo_ + bias[3][cc];
                    float cv = sigmoidf_(gf) * c[k] + sigmoidf_(gi) * tanhf(gg);
                    c[k] = cv;
                    hv2[cc] = sigmoidf_(go) * tanhf(cv);
                }
                if (L0) {
                    *(float2*)(hout + ((size_t)(t * BB + b)) * 1024 + grp * 512 + j0 + u) =
                        make_float2(hv2[0], hv2[1]);
                } else if (t == TT - 1) {
                    *(float2*)(hout + (size_t)b * HH + j0 + u) =
                        make_float2(hv2[0], hv2[1]);
                }
                *(uint32_t*)(dh + (size_t)b * HH + j0 + u) = pack_h2(hv2[0], hv2[1]);
            }
        }

        if (step < TT - 1) {
            __threadfence();
            __syncthreads();
            if (tid == 0) {
                atomicAdd(barp + step, 1);
                while (((volatile int*)barp)[step] < 64) {}
            }
            __syncthreads();
        }
    }
}

// ========================= layer-1 reverse at t = T-1 ========================
__global__ void hr_last_kernel(const float* __restrict__ xg,
                               const float* __restrict__ bhh,
                               float* __restrict__ hr) {
    int idx = blockIdx.x * blockDim.x + threadIdx.x;
    if (idx >= BB * HH) return;
    int b = idx >> 9, j = idx & 511;
    float gi = xg[(size_t)b * G4H + j]        + bhh[j];
    float gg = xg[(size_t)b * G4H + 1024 + j] + bhh[1024 + j];
    float go = xg[(size_t)b * G4H + 1536 + j] + bhh[1536 + j];
    float cv = sigmoidf_(gi) * tanhf(gg);
    hr[idx] = sigmoidf_(go) * tanhf(cv);
}

// ========================= final projection ==================================
__global__ void out_kernel(const float* __restrict__ hf, const float* __restrict__ hr,
                           const float* __restrict__ wout, const float* __restrict__ bout,
                           float* __restrict__ out) {
    int b = blockIdx.x;
    int warp = threadIdx.x >> 5;
    int lane = threadIdx.x & 31;
    float s = 0.f;
    for (int k = lane; k < 512; k += 32) s += hf[(size_t)b * HH + k] * wout[warp * 1024 + k];
    for (int k = lane; k < 512; k += 32) s += hr[(size_t)b * HH + k] * wout[warp * 1024 + 512 + k];
#pragma unroll
    for (int off = 16; off; off >>= 1) s += __shfl_xor_sync(0xffffffffu, s, off);
    if (lane == 0) out[b * NCLS + warp] = s + bout[warp];
}

// ========================= host launch =======================================
extern "C" void kernel_launch(void* const* d_in, const int* in_sizes, int n_in,
                              void* d_out, int out_size) {
    const int*   x     = (const int*)  d_in[0];
    const float* emb   = (const float*)d_in[1];
    const float* wih0f = (const float*)d_in[2];
    const float* whh0f = (const float*)d_in[3];
    const float* bih0f = (const float*)d_in[4];
    const float* bhh0f = (const float*)d_in[5];
    const float* wih0r = (const float*)d_in[6];
    const float* whh0r = (const float*)d_in[7];
    const float* bih0r = (const float*)d_in[8];
    const float* bhh0r = (const float*)d_in[9];
    const float* wih1f = (const float*)d_in[10];
    const float* whh1f = (const float*)d_in[11];
    const float* bih1f = (const float*)d_in[12];
    const float* bhh1f = (const float*)d_in[13];
    const float* wih1r = (const float*)d_in[14];
    const float* whh1r = (const float*)d_in[15]; (void)whh1r;
    const float* bih1r = (const float*)d_in[16];
    const float* bhh1r = (const float*)d_in[17];
    const float* wout  = (const float*)d_in[18];
    const float* bout  = (const float*)d_in[19];
    float* out = (float*)d_out;

    float *p_x0, *p_xg0f, *p_xg0r, *p_h0, *p_xg1f, *p_xg1r, *p_h1f, *p_hr1;
    __half *p_hf0, *p_hf1;
    int *p_bar0, *p_bar1;
    cudaGetSymbolAddress((void**)&p_x0,   g_x0);
    cudaGetSymbolAddress((void**)&p_xg0f, g_xg0f);
    cudaGetSymbolAddress((void**)&p_xg0r, g_xg0r);
    cudaGetSymbolAddress((void**)&p_h0,   g_h0);
    cudaGetSymbolAddress((void**)&p_xg1f, g_xg1f);
    cudaGetSymbolAddress((void**)&p_xg1r, g_xg1r);
    cudaGetSymbolAddress((void**)&p_h1f,  g_h1f);
    cudaGetSymbolAddress((void**)&p_hr1,  g_hr1);
    cudaGetSymbolAddress((void**)&p_hf0,  g_hf0);
    cudaGetSymbolAddress((void**)&p_hf1,  g_hf1);
    cudaGetSymbolAddress((void**)&p_bar0, g_bar0);
    cudaGetSymbolAddress((void**)&p_bar1, g_bar1);

    cudaFuncSetAttribute(scan_mma<true>,  cudaFuncAttributeMaxDynamicSharedMemorySize, SCAN0_SMEM);
    cudaFuncSetAttribute(scan_mma<false>, cudaFuncAttributeMaxDynamicSharedMemorySize, SCAN1_SMEM);

    reset_kernel<<<1, 512>>>();
    embed_kernel<<<(TT * BB * (DEMB / 4) + 255) / 256, 256>>>(x, emb, p_x0);

    dim3 gBig(G4H / 128, (TT * BB) / 128);   // (16, 256)
    gemm_mma<<<gBig, 256>>>(p_x0, wih0f, bih0f, p_xg0f, TT * BB, G4H, DEMB);
    gemm_mma<<<gBig, 256>>>(p_x0, wih0r, bih0r, p_xg0r, TT * BB, G4H, DEMB);

    scan_mma<true><<<128, 256, SCAN0_SMEM>>>(p_xg0f, p_xg0r, whh0f, whh0r,
                                             bhh0f, bhh0r, p_hf0, p_h0, p_bar0);

    gemm_mma<<<gBig, 256>>>(p_h0, wih1f, bih1f, p_xg1f, TT * BB, G4H, 2 * HH);
    gemm_mma<<<dim3(G4H / 128, 1), 256>>>(
        p_h0 + (size_t)(TT - 1) * BB * 1024, wih1r, bih1r, p_xg1r, BB, G4H, 2 * HH);

    scan_mma<false><<<128, 256, SCAN1_SMEM>>>(p_xg1f, p_xg1f, whh1f, whh1f,
                                              bhh1f, bhh1f, p_hf1, p_h1f, p_bar1);

    hr_last_kernel<<<(BB * HH) / 256, 256>>>(p_xg1r, bhh1r, p_hr1);

    out_kernel<<<BB, 160>>>(p_h1f, p_hr1, wout, bout, out);
}

// round 7
// speedup vs baseline: 3.6914x; 1.0416x over previous
#include <cuda_runtime.h>
#include <cuda_fp16.h>
#include <math.h>
#include <cstdint>

#define TT 256
#define BB 128
#define HH 512
#define DEMB 256
#define PAD_IDX 29999
#define NCLS 5
#define G4H 2048  // 4*HH

__device__ __forceinline__ uint32_t smem_to_u32(const void* p) {
    uint32_t a;
    asm("{ .reg .u64 t; cvta.to.shared.u64 t, %1; cvt.u32.u64 %0, t; }" : "=r"(a) : "l"(p));
    return a;
}
#define CP_ASYNC16(dst, src) \
    asm volatile("cp.async.cg.shared.global [%0], [%1], 16;" :: "r"(dst), "l"(src))
#define CP_COMMIT  asm volatile("cp.async.commit_group;" ::: "memory")
#define CP_WAIT_1  asm volatile("cp.async.wait_group 1;" ::: "memory")
#define CP_WAIT_0  asm volatile("cp.async.wait_group 0;" ::: "memory")

// ========================= scratch (static, no allocs) =======================
__device__ __half g_x0 [(size_t)TT * BB * DEMB];    // embedded input fp16
__device__ float g_xg0f[(size_t)TT * BB * G4H];
__device__ float g_xg0r[(size_t)TT * BB * G4H];
__device__ __half g_h0 [(size_t)TT * BB * 2 * HH];  // layer0 h history fp16 (GEMM A)
__device__ float g_xg1f[(size_t)TT * BB * G4H];
__device__ float g_xg1r[(size_t)BB * G4H];
__device__ __half g_hf0[2 * 2 * BB * HH];  // layer0 recurrent fp16 [dir][parity]
__device__ __half g_hf1[2 * BB * HH];      // layer1 recurrent fp16 [parity]
__device__ float g_h1f [BB * HH];          // layer1 final fwd state fp32
__device__ float g_hr1 [BB * HH];
__device__ int g_bar0[2 * TT];
__device__ int g_bar1[2 * TT];

__global__ void reset_kernel() {
    int i = threadIdx.x;
    if (i < 2 * TT) { g_bar0[i] = 0; g_bar1[i] = 0; }
}

__device__ __forceinline__ uint32_t pack_h2(float a, float b) {
    __half2 h = __floats2half2_rn(a, b);
    return *(uint32_t*)&h;
}

// ========================= embedding gather (fp16 out) =======================
__global__ void embed_kernel(const int* __restrict__ x,
                             const float* __restrict__ emb,
                             __half* __restrict__ out) {
    int gid = blockIdx.x * blockDim.x + threadIdx.x;
    if (gid >= TT * BB * (DEMB / 4)) return;
    int i4  = gid & 63;
    int row = gid >> 6;
    int t = row / BB;
    int b = row - t * BB;
    int xi = x[b * TT + t];
    float4 v;
    if (xi == PAD_IDX) { v.x = v.y = v.z = v.w = 0.f; }
    else               { v = ((const float4*)emb)[(size_t)xi * 64 + i4]; }
    uint2 p;
    p.x = pack_h2(v.x, v.y);
    p.y = pack_h2(v.z, v.w);
    ((uint2*)out)[gid] = p;
}

// ========================= mma primitives ====================================
__device__ __forceinline__ void ldsm4(uint32_t* r, uint32_t addr) {
    asm volatile("ldmatrix.sync.aligned.m8n8.x4.shared.b16 {%0,%1,%2,%3}, [%4];"
        : "=r"(r[0]), "=r"(r[1]), "=r"(r[2]), "=r"(r[3]) : "r"(addr));
}
__device__ __forceinline__ void mma_f16(float* d, const uint32_t* a,
                                        uint32_t b0, uint32_t b1) {
    asm volatile("mma.sync.aligned.m16n8k16.row.col.f32.f16.f16.f32 "
        "{%0,%1,%2,%3}, {%4,%5,%6,%7}, {%8,%9}, {%0,%1,%2,%3};"
        : "+f"(d[0]), "+f"(d[1]), "+f"(d[2]), "+f"(d[3])
        : "r"(a[0]), "r"(a[1]), "r"(a[2]), "r"(a[3]), "r"(b0), "r"(b1));
}
// W: fp16 hi + lo residual pair store (8B each)
__device__ __forceinline__ void splitw_store(uint32_t hiA, uint32_t loA, float4 v) {
    __half h0 = __float2half_rn(v.x), h1 = __float2half_rn(v.y);
    __half h2 = __float2half_rn(v.z), h3 = __float2half_rn(v.w);
    float r0 = v.x - __half2float(h0), r1 = v.y - __half2float(h1);
    float r2 = v.z - __half2float(h2), r3 = v.w - __half2float(h3);
    uint32_t hp0 = pack_h2(__half2float(h0), __half2float(h1));
    uint32_t hp1 = pack_h2(__half2float(h2), __half2float(h3));
    uint32_t lp0 = pack_h2(r0, r1);
    uint32_t lp1 = pack_h2(r2, r3);
    asm volatile("st.shared.v2.b32 [%0], {%1, %2};" :: "r"(hiA), "r"(hp0), "r"(hp1) : "memory");
    asm volatile("st.shared.v2.b32 [%0], {%1, %2};" :: "r"(loA), "r"(lp0), "r"(lp1) : "memory");
}

// ========================= fp16-A GEMM: C = A*W^T + bias =====================
// A fp16 [M,K] (cp.async, double-buffered), W fp32 [N,K] (reg prefetch, hi/lo),
// C fp32 [M,N]. Tile 128x128, 8 warps (4x2).
#define KC  32
#define LDH 40
#define GA_BYTES (128 * LDH * 2)

__global__ __launch_bounds__(256, 2) void gemm_mma(const __half* __restrict__ A,
                                                   const float* __restrict__ W,
                                                   const float* __restrict__ bias,
                                                   float* __restrict__ C,
                                                   int M, int N, int K) {
    __shared__ __align__(16) __half gsm[4 * 128 * LDH];
    const uint32_t sb  = smem_to_u32(gsm);
    const uint32_t AH0 = sb, AH1 = sb + GA_BYTES;
    const uint32_t BH  = sb + 2 * GA_BYTES, BL = BH + GA_BYTES;

    const int tid  = threadIdx.x;
    const int lane = tid & 31;
    const int wid  = tid >> 5;
    const int wm   = wid & 3;
    const int wn   = wid >> 2;
    const int bm   = blockIdx.y * 128;
    const int bn   = blockIdx.x * 128;

    float acc[2][8][4];
#pragma unroll
    for (int i = 0; i < 2; i++)
#pragma unroll
        for (int j = 0; j < 8; j++)
#pragma unroll
            for (int k = 0; k < 4; k++) acc[i][j][k] = 0.f;

    const uint32_t a_row = lane & 15;
    const uint32_t a_col = (lane >> 4) << 3;
    const uint32_t b_n   = (lane & 7) + ((lane >> 4) << 3);
    const uint32_t b_k   = ((lane >> 3) & 1) << 3;

    const int s_row = tid >> 2, s_c8 = tid & 3;
    const int w_row = tid >> 3, w_c4 = tid & 7;

    float4 vw[4];
#pragma unroll
    for (int i = 0; i < 2; i++) {
        int row = s_row + i * 64;
        CP_ASYNC16(AH0 + (row * LDH + s_c8 * 8) * 2,
                   A + (size_t)(bm + row) * K + s_c8 * 8);
    }
    CP_COMMIT;
#pragma unroll
    for (int i = 0; i < 4; i++) {
        int row = w_row + i * 32;
        vw[i] = *(const float4*)(W + (size_t)(bn + row) * K + w_c4 * 4);
    }

    const int nch = K / KC;
    for (int ch = 0; ch < nch; ch++) {
        const int kb = ch * KC;
        if (ch + 1 < nch) {
            uint32_t dst = ((ch + 1) & 1) ? AH1 : AH0;
#pragma unroll
            for (int i = 0; i < 2; i++) {
                int row = s_row + i * 64;
                CP_ASYNC16(dst + (row * LDH + s_c8 * 8) * 2,
                           A + (size_t)(bm + row) * K + kb + KC + s_c8 * 8);
            }
            CP_COMMIT;
        }
#pragma unroll
        for (int i = 0; i < 4; i++) {
            int row = w_row + i * 32;
            uint32_t off = (row * LDH + w_c4 * 4) * 2;
            splitw_store(BH + off, BL + off, vw[i]);
        }
        if (ch + 1 < nch) {
#pragma unroll
            for (int i = 0; i < 4; i++) {
                int row = w_row + i * 32;
                vw[i] = *(const float4*)(W + (size_t)(bn + row) * K + kb + KC + w_c4 * 4);
            }
        }
        if (ch + 1 < nch) { CP_WAIT_1; } else { CP_WAIT_0; }
        __syncthreads();

        const uint32_t AH = (ch & 1) ? AH1 : AH0;
#pragma unroll
        for (int ks = 0; ks < KC; ks += 16) {
            uint32_t ah[2][4];
#pragma unroll
            for (int ma = 0; ma < 2; ma++)
                ldsm4(ah[ma], AH + ((wm * 32 + ma * 16 + a_row) * LDH + ks + a_col) * 2);
#pragma unroll
            for (int bg = 0; bg < 4; bg++) {
                uint32_t boff = ((wn * 64 + bg * 16 + b_n) * LDH + ks + b_k) * 2;
                uint32_t bh[4], bl[4];
                ldsm4(bh, BH + boff);
                ldsm4(bl, BL + boff);
#pragma unroll
                for (int ma = 0; ma < 2; ma++) {
#pragma unroll
                    for (int na = 0; na < 2; na++) {
                        float* d = acc[ma][bg * 2 + na];
                        mma_f16(d, ah[ma], bh[na * 2], bh[na * 2 + 1]);
                        mma_f16(d, ah[ma], bl[na * 2], bl[na * 2 + 1]);
                    }
                }
            }
        }
        __syncthreads();
    }

#pragma unroll
    for (int ma = 0; ma < 2; ma++) {
        int row0 = bm + wm * 32 + ma * 16 + (lane >> 2);
#pragma unroll
        for (int na = 0; na < 8; na++) {
            int col = bn + wn * 64 + na * 8 + (lane & 3) * 2;
            float b0 = bias[col], b1 = bias[col + 1];
            float2 v0 = make_float2(acc[ma][na][0] + b0, acc[ma][na][1] + b1);
            float2 v1 = make_float2(acc[ma][na][2] + b0, acc[ma][na][3] + b1);
            *(float2*)(C + (size_t)row0 * N + col) = v0;
            *(float2*)(C + (size_t)(row0 + 8) * N + col) = v1;
        }
    }
}

__device__ __forceinline__ float sigmoidf_(float v) { return 1.f / (1.f + expf(-v)); }

// ========================= tensor-core LSTM scan (PROVEN R5 machinery) =======
#define W_STR 520
#define A_STR 264
#define W_SPL_BYTES (32 * W_STR * 2)
#define SCAN_W_BYTES (2 * W_SPL_BYTES)                    // 66560
#define SCAN0_SMEM (SCAN_W_BYTES + 2 * 128 * A_STR * 2)   // 201728
#define SCAN1_SMEM (SCAN_W_BYTES + 2 * 64 * A_STR * 2)    // 134144

template<int MC>
__device__ __forceinline__ void stage_chunk(uint32_t dst, const __half* hs,
                                            int bbase, int kb, int tid) {
#pragma unroll
    for (int i = 0; i < MC / 8; i++) {
        int e = tid + i * 256;
        int row = e >> 5, seg = e & 31;
        const __half* src = hs + (size_t)(bbase + row) * HH + kb + seg * 8;
        CP_ASYNC16(dst + (row * A_STR + seg * 8) * 2, src);
    }
}

__device__ __forceinline__ void mma_chunk(uint32_t AB, uint32_t WHI, uint32_t WLO,
                                          int mrow, int kg0,
                                          uint32_t a_row, uint32_t a_col,
                                          uint32_t b_n, uint32_t b_k,
                                          float acc[4][4]) {
#pragma unroll
    for (int kk = 0; kk < 16; kk++) {
        uint32_t a[4];
        ldsm4(a, AB + ((mrow + a_row) * A_STR + kk * 16 + a_col) * 2);
        int kg = kg0 + kk * 16;
        uint32_t bh0[4], bh1[4], bl0[4], bl1[4];
        ldsm4(bh0, WHI + (b_n * W_STR + kg + b_k) * 2);
        ldsm4(bh1, WHI + ((16 + b_n) * W_STR + kg + b_k) * 2);
        ldsm4(bl0, WLO + (b_n * W_STR + kg + b_k) * 2);
        ldsm4(bl1, WLO + ((16 + b_n) * W_STR + kg + b_k) * 2);
        mma_f16(acc[0], a, bh0[0], bh0[1]);
        mma_f16(acc[0], a, bl0[0], bl0[1]);
        mma_f16(acc[1], a, bh0[2], bh0[3]);
        mma_f16(acc[1], a, bl0[2], bl0[3]);
        mma_f16(acc[2], a, bh1[0], bh1[1]);
        mma_f16(acc[2], a, bl1[0], bl1[1]);
        mma_f16(acc[3], a, bh1[2], bh1[3]);
        mma_f16(acc[3], a, bl1[2], bl1[3]);
    }
}

template<bool L0>
__global__ __launch_bounds__(256, 1) void scan_mma(
    const float* __restrict__ xgf, const float* __restrict__ xgr,
    const float* __restrict__ whhf, const float* __restrict__ whhr,
    const float* __restrict__ bhhf, const float* __restrict__ bhhr,
    __half* __restrict__ hrec, float* __restrict__ houtf,
    __half* __restrict__ houth, int* __restrict__ bar) {
    constexpr int MC = L0 ? 128 : 64;
    constexpr int ASZ = MC * A_STR * 2;
    extern __shared__ __align__(16) char smem[];
    const uint32_t sb  = smem_to_u32(smem);
    const uint32_t WHI = sb, WLO = sb + W_SPL_BYTES;
    const uint32_t AB0 = sb + SCAN_W_BYTES, AB1 = AB0 + ASZ;

    const int tid = threadIdx.x, lane = tid & 31, wid = tid >> 5;
    const int grp   = blockIdx.x >> 6;
    const int slice = blockIdx.x & 63;
    const int j0    = slice * 8;
    const int bbase = L0 ? 0 : grp * 64;

    const float* whh = (L0 && grp) ? whhr : whhf;
    const float* bhh = (L0 && grp) ? bhhr : bhhf;
    const float* xg  = (L0 && grp) ? xgr  : xgf;
    int* barp = bar + grp * TT;
    __half* hbuf = hrec + (L0 ? (size_t)grp * 2 * BB * HH : 0);

#pragma unroll
    for (int i = 0; i < 16; i++) {
        int idx = tid + i * 256;
        int n = idx >> 7, c4 = idx & 127;
        int grow = (n >> 3) * 512 + j0 + (n & 7);
        float4 v = *(const float4*)(whh + (size_t)grow * 512 + c4 * 4);
        uint32_t off = (n * W_STR + c4 * 4) * 2;
        splitw_store(WHI + off, WLO + off, v);
    }
    __syncthreads();

    const uint32_t a_row = lane & 15;
    const uint32_t a_col = (lane >> 4) << 3;
    const uint32_t b_n   = (lane & 7) + ((lane >> 4) << 3);
    const uint32_t b_k   = ((lane >> 3) & 1) << 3;
    const int r = lane >> 2;
    const int u = (lane & 3) * 2;
    const int wm = L0 ? wid : (wid & 3);
    const int mrow = wm * 16;
    const bool owner = L0 || (wid < 4);

    float bias[4][2];
#pragma unroll
    for (int g = 0; g < 4; g++) {
        bias[g][0] = bhh[g * 512 + j0 + u];
        bias[g][1] = bhh[g * 512 + j0 + u + 1];
    }
    float c[4] = {0.f, 0.f, 0.f, 0.f};

    for (int step = 0; step < TT; step++) {
        const int t = (L0 && grp) ? (TT - 1 - step) : step;

        float2 xv[4][2];
        if (owner) {
            const float* xp = xg + ((size_t)(t * BB + bbase + mrow + r)) * G4H + j0 + u;
#pragma unroll
            for (int g = 0; g < 4; g++)
#pragma unroll
                for (int rp = 0; rp < 2; rp++)
                    xv[g][rp] = *(const float2*)(xp + (size_t)rp * 8 * G4H + g * 512);
        }

        float acc[4][4];
#pragma unroll
        for (int g = 0; g < 4; g++)
#pragma unroll
            for (int k = 0; k < 4; k++) acc[g][k] = 0.f;

        if (step > 0) {
            const int rpar = (step - 1) & 1;
            const __half* hs = hbuf + (size_t)rpar * BB * HH;
            stage_chunk<MC>(AB0, hs, bbase, 0, tid);   CP_COMMIT;
            stage_chunk<MC>(AB1, hs, bbase, 256, tid); CP_COMMIT;
            if (L0) {
                CP_WAIT_1;
                __syncthreads();
                mma_chunk(AB0, WHI, WLO, mrow, 0, a_row, a_col, b_n, b_k, acc);
                CP_WAIT_0;
                __syncthreads();
                mma_chunk(AB1, WHI, WLO, mrow, 256, a_row, a_col, b_n, b_k, acc);
            } else {
                CP_WAIT_0;
                __syncthreads();
                const int ks = wid >> 2;
                mma_chunk(ks ? AB1 : AB0, WHI, WLO, mrow, ks * 256,
                          a_row, a_col, b_n, b_k, acc);
            }
        }

        if (!L0) {
            __syncthreads();
            if (wid >= 4) {
                uint32_t base = AB0 + ((wid - 4) * 32 + lane) * 4;
#pragma unroll
                for (int f = 0; f < 16; f++)
                    *(float*)(smem + (base - sb) + f * 512) = acc[f >> 2][f & 3];
            }
            __syncthreads();
            if (wid < 4) {
                uint32_t base = AB0 + (wid * 32 + lane) * 4;
#pragma unroll
                for (int f = 0; f < 16; f++)
                    acc[f >> 2][f & 3] += *(float*)(smem + (base - sb) + f * 512);
            }
        }

        if (owner) {
            const int wpar = step & 1;
            __half* dh = hbuf + (size_t)wpar * BB * HH;
#pragma unroll
            for (int rp = 0; rp < 2; rp++) {
                const int b = bbase + mrow + r + rp * 8;
                float hv2[2];
#pragma unroll
                for (int cc = 0; cc < 2; cc++) {
                    const int k = rp * 2 + cc;
                    float xi_ = cc ? xv[0][rp].y : xv[0][rp].x;
                    float xf_ = cc ? xv[1][rp].y : xv[1][rp].x;
                    float xg_ = cc ? xv[2][rp].y : xv[2][rp].x;
                    float xo_ = cc ? xv[3][rp].y : xv[3][rp].x;
                    float gi = acc[0][k] + xi_ + bias[0][cc];
                    float gf = acc[1][k] + xf_ + bias[1][cc];
                    float gg = acc[2][k] + xg_ + bias[2][cc];
                    float go = acc[3][k] + xo_ + bias[3][cc];
                    float cv = sigmoidf_(gf) * c[k] + sigmoidf_(gi) * tanhf(gg);
                    c[k] = cv;
                    hv2[cc] = sigmoidf_(go) * tanhf(cv);
                }
                if (L0) {
                    // fp16 h0 history for the layer-1 GEMM (same cvt.rn the old
                    // GEMM staging applied -> bit-identical downstream numerics)
                    *(uint32_t*)(houth + ((size_t)(t * BB + b)) * 1024 + grp * 512 + j0 + u) =
                        pack_h2(hv2[0], hv2[1]);
                } else if (t == TT - 1) {
                    *(float2*)(houtf + (size_t)b * HH + j0 + u) =
                        make_float2(hv2[0], hv2[1]);
                }
                *(uint32_t*)(dh + (size_t)b * HH + j0 + u) = pack_h2(hv2[0], hv2[1]);
            }
        }

        if (step < TT - 1) {
            __threadfence();
            __syncthreads();
            if (tid == 0) {
                atomicAdd(barp + step, 1);
                while (((volatile int*)barp)[step] < 64) {}
            }
            __syncthreads();
        }
    }
}

// ========================= layer-1 reverse at t = T-1 ========================
__global__ void hr_last_kernel(const float* __restrict__ xg,
                               const float* __restrict__ bhh,
                               float* __restrict__ hr) {
    int idx = blockIdx.x * blockDim.x + threadIdx.x;
    if (idx >= BB * HH) return;
    int b = idx >> 9, j = idx & 511;
    float gi = xg[(size_t)b * G4H + j]        + bhh[j];
    float gg = xg[(size_t)b * G4H + 1024 + j] + bhh[1024 + j];
    float go = xg[(size_t)b * G4H + 1536 + j] + bhh[1536 + j];
    float cv = sigmoidf_(gi) * tanhf(gg);
    hr[idx] = sigmoidf_(go) * tanhf(cv);
}

// ========================= final projection ==================================
__global__ void out_kernel(const float* __restrict__ hf, const float* __restrict__ hr,
                           const float* __restrict__ wout, const float* __restrict__ bout,
                           float* __restrict__ out) {
    int b = blockIdx.x;
    int warp = threadIdx.x >> 5;
    int lane = threadIdx.x & 31;
    float s = 0.f;
    for (int k = lane; k < 512; k += 32) s += hf[(size_t)b * HH + k] * wout[warp * 1024 + k];
    for (int k = lane; k < 512; k += 32) s += hr[(size_t)b * HH + k] * wout[warp * 1024 + 512 + k];
#pragma unroll
    for (int off = 16; off; off >>= 1) s += __shfl_xor_sync(0xffffffffu, s, off);
    if (lane == 0) out[b * NCLS + warp] = s + bout[warp];
}

// ========================= host launch =======================================
extern "C" void kernel_launch(void* const* d_in, const int* in_sizes, int n_in,
                              void* d_out, int out_size) {
    const int*   x     = (const int*)  d_in[0];
    const float* emb   = (const float*)d_in[1];
    const float* wih0f = (const float*)d_in[2];
    const float* whh0f = (const float*)d_in[3];
    const float* bih0f = (const float*)d_in[4];
    const float* bhh0f = (const float*)d_in[5];
    const float* wih0r = (const float*)d_in[6];
    const float* whh0r = (const float*)d_in[7];
    const float* bih0r = (const float*)d_in[8];
    const float* bhh0r = (const float*)d_in[9];
    const float* wih1f = (const float*)d_in[10];
    const float* whh1f = (const float*)d_in[11];
    const float* bih1f = (const float*)d_in[12];
    const float* bhh1f = (const float*)d_in[13];
    const float* wih1r = (const float*)d_in[14];
    const float* whh1r = (const float*)d_in[15]; (void)whh1r;
    const float* bih1r = (const float*)d_in[16];
    const float* bhh1r = (const float*)d_in[17];
    const float* wout  = (const float*)d_in[18];
    const float* bout  = (const float*)d_in[19];
    float* out = (float*)d_out;

    __half *p_x0, *p_h0, *p_hf0, *p_hf1;
    float *p_xg0f, *p_xg0r, *p_xg1f, *p_xg1r, *p_h1f, *p_hr1;
    int *p_bar0, *p_bar1;
    cudaGetSymbolAddress((void**)&p_x0,   g_x0);
    cudaGetSymbolAddress((void**)&p_xg0f, g_xg0f);
    cudaGetSymbolAddress((void**)&p_xg0r, g_xg0r);
    cudaGetSymbolAddress((void**)&p_h0,   g_h0);
    cudaGetSymbolAddress((void**)&p_xg1f, g_xg1f);
    cudaGetSymbolAddress((void**)&p_xg1r, g_xg1r);
    cudaGetSymbolAddress((void**)&p_hf0,  g_hf0);
    cudaGetSymbolAddress((void**)&p_hf1,  g_hf1);
    cudaGetSymbolAddress((void**)&p_h1f,  g_h1f);
    cudaGetSymbolAddress((void**)&p_hr1,  g_hr1);
    cudaGetSymbolAddress((void**)&p_bar0, g_bar0);
    cudaGetSymbolAddress((void**)&p_bar1, g_bar1);

    cudaFuncSetAttribute(scan_mma<true>,  cudaFuncAttributeMaxDynamicSharedMemorySize, SCAN0_SMEM);
    cudaFuncSetAttribute(scan_mma<false>, cudaFuncAttributeMaxDynamicSharedMemorySize, SCAN1_SMEM);

    reset_kernel<<<1, 512>>>();
    embed_kernel<<<(TT * BB * (DEMB / 4) + 255) / 256, 256>>>(x, emb, p_x0);

    dim3 gBig(G4H / 128, (TT * BB) / 128);   // (16, 256)
    gemm_mma<<<gBig, 256>>>(p_x0, wih0f, bih0f, p_xg0f, TT * BB, G4H, DEMB);
    gemm_mma<<<gBig, 256>>>(p_x0, wih0r, bih0r, p_xg0r, TT * BB, G4H, DEMB);

    scan_mma<true><<<128, 256, SCAN0_SMEM>>>(p_xg0f, p_xg0r, whh0f, whh0r,
                                             bhh0f, bhh0r, p_hf0, nullptr,
                                             p_h0, p_bar0);

    gemm_mma<<<gBig, 256>>>(p_h0, wih1f, bih1f, p_xg1f, TT * BB, G4H, 2 * HH);
    gemm_mma<<<dim3(G4H / 128, 1), 256>>>(
        p_h0 + (size_t)(TT - 1) * BB * 1024, wih1r, bih1r, p_xg1r, BB, G4H, 2 * HH);

    scan_mma<false><<<128, 256, SCAN1_SMEM>>>(p_xg1f, p_xg1f, whh1f, whh1f,
                                              bhh1f, bhh1f, p_hf1, p_h1f,
                                              nullptr, p_bar1);

    hr_last_kernel<<<(BB * HH) / 256, 256>>>(p_xg1r, bhh1r, p_hr1);

    out_kernel<<<BB, 160>>>(p_h1f, p_hr1, wout, bout, out);
}